// round 2
// baseline (speedup 1.0000x reference)
#include <cuda_runtime.h>
#include <math.h>

#define N_NODES 4096
#define E_TYPES 5
#define W_IN 512
#define W_OUT 128
#define NUM_CLASS 16
#define M_TGT 1024
#define NUM_LAYERS 64
#define H0 (W_IN + E_TYPES * W_OUT)   // 1152
#define NNZ_CAP 2097152
#define CAPE 262144                   // per-edge-type CSC capacity
#define NWIN 16                       // column windows of 256
#define WINC 256

// ---------------- static scratch ----------------
__device__ float g_Xg[N_NODES * W_IN];
__device__ float g_Xw[N_NODES * W_OUT];
__device__ float g_lgcn[E_TYPES * N_NODES * W_OUT];
__device__ float g_attpart[E_TYPES * 32 * W_OUT];
__device__ float g_beta[E_TYPES];
__device__ float g_Xcat[N_NODES * H0];
__device__ float g_x0[N_NODES * W_OUT];
__device__ float g_xA[N_NODES * W_OUT];
__device__ float g_xB[N_NODES * W_OUT];
__device__ float g_Z1[N_NODES * W_OUT];
__device__ float g_Z2[N_NODES * W_OUT];
__device__ float g_y[M_TGT * NUM_CLASS];
__device__ int   g_cnt[N_NODES];
__device__ int   g_rowptr[N_NODES + 1];
__device__ float g_dis[N_NODES];
__device__ int   g_col[NNZ_CAP];
__device__ float g_val[NNZ_CAP];
__device__ int   g_zinit[3 * E_TYPES * N_NODES];    // ccnt | cfill | degsum(float)
__device__ int   g_cptr[E_TYPES * (N_NODES + 1)];
__device__ int   g_csrc[E_TYPES * CAPE];
__device__ float g_cval[E_TYPES * CAPE];
__device__ int   g_wstart[N_NODES * (NWIN + 1)];
__device__ float g_part[NWIN * N_NODES * W_OUT];    // 32MB

// ---------------- 128x128x16 register-tiled GEMM ----------------
// C[M,N] = act(accScale*(A@B) + resScale*Res + bias), act: 0 none, 1 relu, 2 leaky
__global__ __launch_bounds__(256, 2) void gemm128(
    const float* __restrict__ A, const float* __restrict__ B, float* __restrict__ C,
    int M, int N, int K, const float* __restrict__ bias, const float* __restrict__ Res,
    float accScale, float resScale, int act) {
    __shared__ float Ast[16 * 132];
    __shared__ float Bs[16 * 128];
    int bm = blockIdx.y, bn = blockIdx.x;
    int t = threadIdx.x;
    int tx = t & 15, ty = t >> 4;
    int arow = t >> 2, ac4 = (t & 3) << 2;
    int bkr = t >> 5, bc4 = (t & 31) << 2;
    float acc[8][8];
#pragma unroll
    for (int i = 0; i < 8; i++)
#pragma unroll
        for (int j = 0; j < 8; j++) acc[i][j] = 0.f;
    const float* Ab = A + (long long)(bm * 128) * K;
    const float* Bb = B + bn * 128;
    for (int k0 = 0; k0 < K; k0 += 16) {
        float4 a0 = *(const float4*)(Ab + (long long)arow * K + k0 + ac4);
        float4 a1 = *(const float4*)(Ab + (long long)(arow + 64) * K + k0 + ac4);
        float4 b0 = *(const float4*)(Bb + (long long)(k0 + bkr) * N + bc4);
        float4 b1 = *(const float4*)(Bb + (long long)(k0 + bkr + 8) * N + bc4);
        __syncthreads();
        Ast[(ac4 + 0) * 132 + arow] = a0.x;
        Ast[(ac4 + 1) * 132 + arow] = a0.y;
        Ast[(ac4 + 2) * 132 + arow] = a0.z;
        Ast[(ac4 + 3) * 132 + arow] = a0.w;
        Ast[(ac4 + 0) * 132 + arow + 64] = a1.x;
        Ast[(ac4 + 1) * 132 + arow + 64] = a1.y;
        Ast[(ac4 + 2) * 132 + arow + 64] = a1.z;
        Ast[(ac4 + 3) * 132 + arow + 64] = a1.w;
        *(float4*)(Bs + bkr * 128 + bc4) = b0;
        *(float4*)(Bs + (bkr + 8) * 128 + bc4) = b1;
        __syncthreads();
#pragma unroll
        for (int kk = 0; kk < 16; kk++) {
            float4 av0 = *(const float4*)(Ast + kk * 132 + ty * 8);
            float4 av1 = *(const float4*)(Ast + kk * 132 + ty * 8 + 4);
            float a[8] = {av0.x, av0.y, av0.z, av0.w, av1.x, av1.y, av1.z, av1.w};
            float b[8];
#pragma unroll
            for (int j = 0; j < 8; j++) b[j] = Bs[kk * 128 + j * 16 + tx];
#pragma unroll
            for (int i = 0; i < 8; i++)
#pragma unroll
                for (int j = 0; j < 8; j++) acc[i][j] += a[i] * b[j];
        }
    }
#pragma unroll
    for (int i = 0; i < 8; i++) {
        long long r = bm * 128 + ty * 8 + i;
#pragma unroll
        for (int j = 0; j < 8; j++) {
            int c = bn * 128 + j * 16 + tx;
            float v = accScale * acc[i][j];
            if (Res)  v += resScale * Res[r * N + c];
            if (bias) v += bias[c];
            if (act == 1) v = fmaxf(v, 0.f);
            else if (act == 2) v = (v >= 0.f) ? v : 0.01f * v;
            C[r * N + c] = v;
        }
    }
}

// ---------------- union CSR rowcount + per-e CSC colcount + degsum ----------------
__global__ void rowcnt_ext(const float* __restrict__ A, int* __restrict__ cnt,
                           float* __restrict__ dis, int* __restrict__ ccnt,
                           float* __restrict__ degsum) {
    int i = blockIdx.x;
    int tid = threadIdx.x;                 // 256
    int c = 0;
    for (int j = tid; j < N_NODES; j += 256) {
        const float* ap = A + ((long long)i * N_NODES + j) * E_TYPES;
        float a[E_TYPES];
#pragma unroll
        for (int e = 0; e < E_TYPES; e++) a[e] = ap[e];
        bool nz = (j == i);
#pragma unroll
        for (int e = 0; e < E_TYPES; e++) nz |= (a[e] != 0.f);
        c += nz ? 1 : 0;
        if (j != i) {
#pragma unroll
            for (int e = 0; e < E_TYPES; e++) {
                if (a[e] != 0.f) {
                    atomicAdd(&ccnt[e * N_NODES + j], 1);
                    atomicAdd(&degsum[e * N_NODES + j], a[e]);
                }
            }
        }
    }
    __shared__ int red[256];
    red[tid] = c;
    __syncthreads();
    for (int o = 128; o; o >>= 1) {
        if (tid < o) red[tid] += red[tid + o];
        __syncthreads();
    }
    if (tid == 0) {
        cnt[i] = red[0];
        dis[i] = rsqrtf((float)red[0]);
    }
}

__global__ void scan_kernel(const int* __restrict__ cnt, int* __restrict__ rowptr) {
    __shared__ int warpsum[32];
    int t = threadIdx.x;                   // 1024, 4 elems each
    int v[4], s = 0;
#pragma unroll
    for (int j = 0; j < 4; j++) { v[j] = cnt[t * 4 + j]; s += v[j]; }
    int lane = t & 31, warp = t >> 5;
    int x = s;
#pragma unroll
    for (int o = 1; o < 32; o <<= 1) {
        int y = __shfl_up_sync(0xffffffffu, x, o);
        if (lane >= o) x += y;
    }
    if (lane == 31) warpsum[warp] = x;
    __syncthreads();
    if (warp == 0) {
        int w = warpsum[lane];
#pragma unroll
        for (int o = 1; o < 32; o <<= 1) {
            int y = __shfl_up_sync(0xffffffffu, w, o);
            if (lane >= o) w += y;
        }
        warpsum[lane] = w;
    }
    __syncthreads();
    int excl = x - s + (warp ? warpsum[warp - 1] : 0);
    int run = excl;
    if (t == 0) rowptr[0] = 0;
#pragma unroll
    for (int j = 0; j < 4; j++) { run += v[j]; rowptr[t * 4 + j + 1] = run; }
}

// ---------------- union CSR fill + per-e CSC fill ----------------
__global__ void fill_ext(const float* __restrict__ A, const int* __restrict__ rowptr,
                         const float* __restrict__ dis, int* __restrict__ col,
                         float* __restrict__ val, const int* __restrict__ cptr,
                         int* __restrict__ cfill, int* __restrict__ csrc,
                         float* __restrict__ cval) {
    int i = blockIdx.x;
    float di = dis[i];
    __shared__ int warpCnt[8];
    __shared__ int blockBase;
    if (threadIdx.x == 0) blockBase = rowptr[i];
    __syncthreads();
    for (int j0 = 0; j0 < N_NODES; j0 += 256) {
        int j = j0 + threadIdx.x;
        const float* ap = A + ((long long)i * N_NODES + j) * E_TYPES;
        float a[E_TYPES];
#pragma unroll
        for (int e = 0; e < E_TYPES; e++) a[e] = ap[e];
        bool nz = (j == i);
#pragma unroll
        for (int e = 0; e < E_TYPES; e++) nz |= (a[e] != 0.f);
        // per-e CSC (exclude diagonal)
        if (j != i) {
#pragma unroll
            for (int e = 0; e < E_TYPES; e++) {
                if (a[e] != 0.f) {
                    int slot = atomicAdd(&cfill[e * N_NODES + j], 1);
                    int pos = cptr[e * (N_NODES + 1) + j] + slot;
                    csrc[e * CAPE + pos] = i;
                    cval[e * CAPE + pos] = a[e];
                }
            }
        }
        unsigned mask = __ballot_sync(0xffffffffu, nz);
        int warp = threadIdx.x >> 5, lane = threadIdx.x & 31;
        if (lane == 0) warpCnt[warp] = __popc(mask);
        __syncthreads();
        int woff = 0;
        for (int w = 0; w < warp; w++) woff += warpCnt[w];
        int total = 0;
        for (int w = 0; w < 8; w++) total += warpCnt[w];
        if (nz) {
            int pos = blockBase + woff + __popc(mask & ((1u << lane) - 1));
            col[pos] = j;
            val[pos] = di * dis[j];
        }
        __syncthreads();
        if (threadIdx.x == 0) blockBase += total;
        __syncthreads();
    }
}

// ---------------- per-row window boundaries (binary search) ----------------
__global__ void window_index(const int* __restrict__ rowptr, const int* __restrict__ col,
                             int* __restrict__ wstart) {
    int t = blockIdx.x * 256 + threadIdx.x;
    if (t >= N_NODES * (NWIN + 1)) return;
    int row = t / (NWIN + 1), w = t % (NWIN + 1);
    int rs = rowptr[row], re = rowptr[row + 1];
    int res;
    if (w == 0) res = rs;
    else if (w == NWIN) res = re;
    else {
        int target = w * WINC;
        int lo = rs, hi = re;
        while (lo < hi) {
            int mid = (lo + hi) >> 1;
            if (col[mid] < target) lo = mid + 1; else hi = mid;
        }
        res = lo;
    }
    wstart[t] = res;
}

// ---------------- lgcn via per-e CSC gather ----------------
__global__ void lgcn_csc(const float* __restrict__ Xw, const int* __restrict__ csrc,
                         const float* __restrict__ cval, const int* __restrict__ cptr,
                         const float* __restrict__ degsum, float* __restrict__ lgcn) {
    int n = blockIdx.x, e = blockIdx.y, d = threadIdx.x;  // 128
    int s = cptr[e * (N_NODES + 1) + n], en = cptr[e * (N_NODES + 1) + n + 1];
    const int* cs = csrc + (long long)e * CAPE;
    const float* cv = cval + (long long)e * CAPE;
    float acc = Xw[(long long)n * W_OUT + d];
    for (int k = s; k < en; k++)
        acc += cv[k] * Xw[(long long)cs[k] * W_OUT + d];
    float dv = 1.f / (1.f + degsum[e * N_NODES + n]);
    lgcn[((long long)e * N_NODES + n) * W_OUT + d] = fmaxf(acc * dv, 0.f);
}

// ---------------- attention: two-stage ----------------
__global__ void att1(const float* __restrict__ lgcn, const float* __restrict__ attw,
                     float* __restrict__ attpart) {
    int g = blockIdx.x, e = blockIdx.y, d = threadIdx.x;  // 128
    float s = 0.f;
    int n0 = g * 128;
    for (int n = n0; n < n0 + 128; n++)
        s += attw[n] * lgcn[((long long)e * N_NODES + n) * W_OUT + d];
    attpart[(e * 32 + g) * W_OUT + d] = s;
}

__global__ void att2(const float* __restrict__ attpart, const float* __restrict__ attb,
                     const float* __restrict__ attq, float* __restrict__ beta) {
    __shared__ float red[128];
    __shared__ float w[E_TYPES];
    int d = threadIdx.x;  // 128
    for (int e = 0; e < E_TYPES; e++) {
        float tot = 0.f;
#pragma unroll
        for (int g = 0; g < 32; g++) tot += attpart[(e * 32 + g) * W_OUT + d];
        red[d] = tanhf(tot + attb[d]) * attq[d];
        __syncthreads();
        for (int o = 64; o; o >>= 1) {
            if (d < o) red[d] += red[d + o];
            __syncthreads();
        }
        if (d == 0) w[e] = red[0];
        __syncthreads();
    }
    if (d == 0) {
        float mx = w[0];
        for (int e = 1; e < E_TYPES; e++) mx = fmaxf(mx, w[e]);
        float ex[E_TYPES], s = 0.f;
        for (int e = 0; e < E_TYPES; e++) { ex[e] = expf(w[e] - mx); s += ex[e]; }
        for (int e = 0; e < E_TYPES; e++) beta[e] = (float)E_TYPES * ex[e] / s;
    }
}

// ---------------- X_ = [beta*lgcn (e-major) | X] ----------------
__global__ void xcat_kernel(const float* __restrict__ lgcn, const float* __restrict__ X,
                            const float* __restrict__ beta, float* __restrict__ Xcat) {
    long long idx = (long long)blockIdx.x * 256 + threadIdx.x;
    long long total = (long long)N_NODES * H0;
    if (idx >= total) return;
    int n = (int)(idx / H0), c = (int)(idx % H0);
    float v;
    if (c < E_TYPES * W_OUT) {
        int e = c >> 7, d = c & 127;
        v = beta[e] * lgcn[((long long)e * N_NODES + n) * W_OUT + d];
    } else {
        v = X[(long long)n * W_IN + (c - E_TYPES * W_OUT)];
    }
    Xcat[idx] = v;
}

// ---------------- layer SpMM, window-tiled with smem staging ----------------
// part[cs][row][d] = sum over nnz of row with col in window cs of val * x[col][d]
__global__ __launch_bounds__(512, 1) void spmm_part(
    const float* __restrict__ x, const int* __restrict__ colp,
    const float* __restrict__ valp, const int* __restrict__ wstart,
    float* __restrict__ part) {
    extern __shared__ float xs[];          // 256 cols x 128 = 128KB
    int cs = blockIdx.x, rb = blockIdx.y;
    int t = threadIdx.x;                   // 512
    const float4* src = (const float4*)(x + (long long)cs * WINC * W_OUT);
    float4* dst = (float4*)xs;
#pragma unroll
    for (int i = 0; i < 16; i++) dst[t + 512 * i] = src[t + 512 * i];
    __syncthreads();
    int d = t & 127, r4 = t >> 7;
    int cbase = cs << 8;
    for (int it = 0; it < 32; it++) {
        int row = (rb << 7) + (it << 2) + r4;
        int ks = wstart[row * (NWIN + 1) + cs];
        int ke = wstart[row * (NWIN + 1) + cs + 1];
        float acc = 0.f;
        for (int k = ks; k < ke; k++) {
            int c = colp[k];
            acc += valp[k] * xs[((c - cbase) << 7) + d];
        }
        part[((long long)(cs << 12) + row) * W_OUT + d] = acc;
    }
}

// ---------------- layer output: reduce partials + residual + GEMM + epilogue ----------------
// hres = 0.9*sum_cs part + 0.1*x0 ; out = relu((1-bl)*hres + bl*(hres@Wl))
__global__ __launch_bounds__(512, 1) void layer_out(
    const float* __restrict__ part, const float* __restrict__ x0,
    const float* __restrict__ Wl, float bl, float* __restrict__ out) {
    extern __shared__ float sm[];
    float* hs = sm;                        // [128][132] transposed: hs[k*132+r]
    float* Bs = sm + 128 * 132;            // [16][128]
    int bm = blockIdx.x;
    int t = threadIdx.x;                   // 512
    // prologue: build hres tile (transposed) in smem
    for (int f = t; f < 128 * 128; f += 512) {
        int r = f >> 7, k = f & 127;
        long long gidx = (long long)(bm * 128 + r) * W_OUT + k;
        float s = 0.f;
#pragma unroll
        for (int cs = 0; cs < NWIN; cs++)
            s += part[(long long)cs * N_NODES * W_OUT + gidx];
        hs[k * 132 + r] = 0.9f * s + 0.1f * x0[gidx];
    }
    __syncthreads();
    int tx = t & 15, ty = t >> 4;          // ty 0..31
    int bkr = t >> 5, bc4 = (t & 31) << 2;
    float acc[4][8];
#pragma unroll
    for (int i = 0; i < 4; i++)
#pragma unroll
        for (int j = 0; j < 8; j++) acc[i][j] = 0.f;
    for (int k0 = 0; k0 < 128; k0 += 16) {
        float4 bv = *(const float4*)(Wl + (k0 + bkr) * W_OUT + bc4);
        __syncthreads();
        *(float4*)(Bs + bkr * 128 + bc4) = bv;
        __syncthreads();
#pragma unroll
        for (int kk = 0; kk < 16; kk++) {
            float4 av = *(const float4*)(hs + (k0 + kk) * 132 + ty * 4);
            float a[4] = {av.x, av.y, av.z, av.w};
            float b[8];
#pragma unroll
            for (int j = 0; j < 8; j++) b[j] = Bs[kk * 128 + j * 16 + tx];
#pragma unroll
            for (int i = 0; i < 4; i++)
#pragma unroll
                for (int j = 0; j < 8; j++) acc[i][j] += a[i] * b[j];
        }
    }
    float omb = 1.f - bl;
#pragma unroll
    for (int i = 0; i < 4; i++) {
        int rl = ty * 4 + i;
        long long r = bm * 128 + rl;
#pragma unroll
        for (int j = 0; j < 8; j++) {
            int c = j * 16 + tx;
            float v = bl * acc[i][j] + omb * hs[c * 132 + rl];
            out[r * W_OUT + c] = fmaxf(v, 0.f);
        }
    }
}

// ---------------- head ----------------
__global__ void out_kernel(const float* __restrict__ Z, const int* __restrict__ tx,
                           const float* __restrict__ W2, const float* __restrict__ b2,
                           float* __restrict__ y) {
    int r = blockIdx.x;
    int t = threadIdx.x;                   // 128
    __shared__ float z[W_OUT];
    z[t] = Z[(long long)tx[r] * W_OUT + t];
    __syncthreads();
    if (t < NUM_CLASS) {
        float s = b2[t];
        for (int k = 0; k < W_OUT; k++) s += z[k] * W2[k * NUM_CLASS + t];
        y[r * NUM_CLASS + t] = s;
    }
}

__global__ void loss_kernel(const float* __restrict__ y, const int* __restrict__ target,
                            float* __restrict__ out) {
    __shared__ float red[256];
    int tid = threadIdx.x;                 // 256
    float part = 0.f;
    for (int r = tid; r < M_TGT; r += 256) {
        const float* yr = y + r * NUM_CLASS;
        float mx = yr[0];
#pragma unroll
        for (int c = 1; c < NUM_CLASS; c++) mx = fmaxf(mx, yr[c]);
        float se = 0.f;
#pragma unroll
        for (int c = 0; c < NUM_CLASS; c++) se += expf(yr[c] - mx);
        float lse = mx + logf(se);
        part += lse - yr[target[r]];
    }
    red[tid] = part;
    __syncthreads();
    for (int o = 128; o; o >>= 1) {
        if (tid < o) red[tid] += red[tid + o];
        __syncthreads();
    }
    if (tid == 0) out[0] = red[0] / (float)M_TGT;
}

// ---------------- launch ----------------
extern "C" void kernel_launch(void* const* d_in, const int* in_sizes, int n_in,
                              void* d_out, int out_size) {
    const float* A        = (const float*)d_in[0];
    const float* X        = (const float*)d_in[1];
    const int*   target_x = (const int*)d_in[2];
    const int*   target   = (const int*)d_in[3];
    const float* weight   = (const float*)d_in[4];
    const float* attw     = (const float*)d_in[5];
    const float* attb     = (const float*)d_in[6];
    const float* attq     = (const float*)d_in[7];
    const float* Wg       = (const float*)d_in[8];
    const float* bg       = (const float*)d_in[9];
    const float* W0       = (const float*)d_in[10];
    const float* b0       = (const float*)d_in[11];
    const float* Wconvs   = (const float*)d_in[12];
    const float* Wd1      = (const float*)d_in[13];
    const float* bd1      = (const float*)d_in[14];
    const float* W1       = (const float*)d_in[15];
    const float* b1       = (const float*)d_in[16];
    const float* W2       = (const float*)d_in[17];
    const float* b2       = (const float*)d_in[18];

    float *Xg, *Xw, *lgcn, *attpart, *beta, *Xcat, *x0, *xA, *xB, *Z1, *Z2, *ybuf;
    float *dis, *valp, *cvalp, *partp;
    int *cnt, *rowptr, *colp, *zinit, *cptr, *csrcp, *wst;
    cudaGetSymbolAddress((void**)&Xg, g_Xg);
    cudaGetSymbolAddress((void**)&Xw, g_Xw);
    cudaGetSymbolAddress((void**)&lgcn, g_lgcn);
    cudaGetSymbolAddress((void**)&attpart, g_attpart);
    cudaGetSymbolAddress((void**)&beta, g_beta);
    cudaGetSymbolAddress((void**)&Xcat, g_Xcat);
    cudaGetSymbolAddress((void**)&x0, g_x0);
    cudaGetSymbolAddress((void**)&xA, g_xA);
    cudaGetSymbolAddress((void**)&xB, g_xB);
    cudaGetSymbolAddress((void**)&Z1, g_Z1);
    cudaGetSymbolAddress((void**)&Z2, g_Z2);
    cudaGetSymbolAddress((void**)&ybuf, g_y);
    cudaGetSymbolAddress((void**)&cnt, g_cnt);
    cudaGetSymbolAddress((void**)&rowptr, g_rowptr);
    cudaGetSymbolAddress((void**)&dis, g_dis);
    cudaGetSymbolAddress((void**)&colp, g_col);
    cudaGetSymbolAddress((void**)&valp, g_val);
    cudaGetSymbolAddress((void**)&zinit, g_zinit);
    cudaGetSymbolAddress((void**)&cptr, g_cptr);
    cudaGetSymbolAddress((void**)&csrcp, g_csrc);
    cudaGetSymbolAddress((void**)&cvalp, g_cval);
    cudaGetSymbolAddress((void**)&wst, g_wstart);
    cudaGetSymbolAddress((void**)&partp, g_part);

    int* ccnt = zinit;
    int* cfill = zinit + E_TYPES * N_NODES;
    float* degsum = (float*)(zinit + 2 * E_TYPES * N_NODES);

    cudaFuncSetAttribute(spmm_part, cudaFuncAttributeMaxDynamicSharedMemorySize, 131072);
    cudaFuncSetAttribute(layer_out, cudaFuncAttributeMaxDynamicSharedMemorySize,
                         (128 * 132 + 16 * 128) * 4);

    cudaMemsetAsync(zinit, 0, 3 * E_TYPES * N_NODES * sizeof(int));

    // 1) Xg = leaky(X @ Wg + bg), Xw = leaky(Xg @ weight)
    gemm128<<<dim3(W_IN / 128, N_NODES / 128), 256>>>(X, Wg, Xg, N_NODES, W_IN, W_IN,
                                                      bg, nullptr, 1.f, 0.f, 2);
    gemm128<<<dim3(1, N_NODES / 128), 256>>>(Xg, weight, Xw, N_NODES, W_OUT, W_IN,
                                             nullptr, nullptr, 1.f, 0.f, 2);
    // 2) sparse structure build (union CSR + per-e CSC) from one pair of A scans
    rowcnt_ext<<<N_NODES, 256>>>(A, cnt, dis, ccnt, degsum);
    scan_kernel<<<1, 1024>>>(cnt, rowptr);
    for (int e = 0; e < E_TYPES; e++)
        scan_kernel<<<1, 1024>>>(ccnt + e * N_NODES, cptr + e * (N_NODES + 1));
    fill_ext<<<N_NODES, 256>>>(A, rowptr, dis, colp, valp, cptr, cfill, csrcp, cvalp);
    window_index<<<(N_NODES * (NWIN + 1) + 255) / 256, 256>>>(rowptr, colp, wst);
    // 3) lgcn + attention + concat
    lgcn_csc<<<dim3(N_NODES, E_TYPES), 128>>>(Xw, csrcp, cvalp, cptr, degsum, lgcn);
    att1<<<dim3(32, E_TYPES), 128>>>(lgcn, attw, attpart);
    att2<<<1, 128>>>(attpart, attb, attq, beta);
    {
        long long total = (long long)N_NODES * H0;
        xcat_kernel<<<(unsigned)((total + 255) / 256), 256>>>(lgcn, X, beta, Xcat);
    }
    gemm128<<<dim3(1, N_NODES / 128), 256>>>(Xcat, W0, x0, N_NODES, W_OUT, H0,
                                             b0, nullptr, 1.f, 0.f, 1);
    // 4) 64 GCNII layers
    const float* xin = x0;
    float* bufs[2] = {xA, xB};
    for (int l = 0; l < NUM_LAYERS; l++) {
        float bl = logf(0.5f / (float)(l + 1) + 1.f);
        spmm_part<<<dim3(NWIN, N_NODES / 128), 512, 131072>>>(xin, colp, valp, wst, partp);
        float* xout = bufs[l & 1];
        layer_out<<<N_NODES / 128, 512, (128 * 132 + 16 * 128) * 4>>>(partp, x0, Wconvs + (long long)l * W_OUT * W_OUT, bl, xout);
        xin = xout;
    }
    // 5) head
    gemm128<<<dim3(1, N_NODES / 128), 256>>>(xin, Wd1, Z1, N_NODES, W_OUT, W_OUT,
                                             bd1, nullptr, 1.f, 0.f, 2);
    gemm128<<<dim3(1, N_NODES / 128), 256>>>(Z1, W1, Z2, N_NODES, W_OUT, W_OUT,
                                             b1, nullptr, 1.f, 0.f, 2);
    float* yout;
    bool with_loss;
    if (out_size >= M_TGT * NUM_CLASS + 1) { yout = (float*)d_out + 1; with_loss = true; }
    else if (out_size == M_TGT * NUM_CLASS) { yout = (float*)d_out; with_loss = false; }
    else { yout = ybuf; with_loss = true; }
    out_kernel<<<M_TGT, 128>>>(Z2, target_x, W2, b2, yout);
    if (with_loss) loss_kernel<<<1, 256>>>(yout, target, (float*)d_out);
}

// round 4
// speedup vs baseline: 1.6796x; 1.6796x over previous
#include <cuda_runtime.h>
#include <cuda_fp16.h>
#include <math.h>

#define N_NODES 4096
#define E_TYPES 5
#define W_IN 512
#define W_OUT 128
#define NUM_CLASS 16
#define M_TGT 1024
#define NUM_LAYERS 64
#define H0 (W_IN + E_TYPES * W_OUT)   // 1152
#define NNZ_CAP 2097152
#define CAPE 262144                   // per-edge-type CSC capacity

// ---------------- static scratch ----------------
__device__ float g_Xg[N_NODES * W_IN];
__device__ float g_Xw[N_NODES * W_OUT];
__device__ float g_lgcn[E_TYPES * N_NODES * W_OUT];
__device__ float g_attpart[E_TYPES * 32 * W_OUT];
__device__ float g_beta[E_TYPES];
__device__ float g_Xcat[N_NODES * H0];
__device__ float g_x0[N_NODES * W_OUT];
__device__ float g_xA[N_NODES * W_OUT];
__device__ float g_xB[N_NODES * W_OUT];
__device__ __half g_xh0[N_NODES * W_OUT];
__device__ __half g_xhA[N_NODES * W_OUT];
__device__ __half g_xhB[N_NODES * W_OUT];
__device__ float g_Z1[N_NODES * W_OUT];
__device__ float g_Z2[N_NODES * W_OUT];
__device__ float g_y[M_TGT * NUM_CLASS];
__device__ int   g_cnt[N_NODES];
__device__ int   g_rowptr[N_NODES + 1];
__device__ float g_dis[N_NODES];
__device__ int   g_col[NNZ_CAP];
__device__ float g_val[NNZ_CAP];
__device__ int   g_zinit[3 * E_TYPES * N_NODES];    // ccnt | cfill | degsum(float)
__device__ int   g_cptr[E_TYPES * (N_NODES + 1)];
__device__ int   g_csrc[E_TYPES * CAPE];
__device__ float g_cval[E_TYPES * CAPE];

__device__ __forceinline__ float h2_as_f(__half2 h) {
    return __uint_as_float(*(unsigned*)&h);
}

// ---------------- 128x128x16 register-tiled GEMM ----------------
// C[M,N] = act(accScale*(A@B) + resScale*Res + bias), act: 0 none, 1 relu, 2 leaky
__global__ __launch_bounds__(256, 2) void gemm128(
    const float* __restrict__ A, const float* __restrict__ B, float* __restrict__ C,
    int M, int N, int K, const float* __restrict__ bias, const float* __restrict__ Res,
    float accScale, float resScale, int act) {
    __shared__ float Ast[16 * 132];
    __shared__ float Bs[16 * 128];
    int bm = blockIdx.y, bn = blockIdx.x;
    int t = threadIdx.x;
    int tx = t & 15, ty = t >> 4;
    int arow = t >> 2, ac4 = (t & 3) << 2;
    int bkr = t >> 5, bc4 = (t & 31) << 2;
    float acc[8][8];
#pragma unroll
    for (int i = 0; i < 8; i++)
#pragma unroll
        for (int j = 0; j < 8; j++) acc[i][j] = 0.f;
    const float* Ab = A + (long long)(bm * 128) * K;
    const float* Bb = B + bn * 128;
    for (int k0 = 0; k0 < K; k0 += 16) {
        float4 a0 = *(const float4*)(Ab + (long long)arow * K + k0 + ac4);
        float4 a1 = *(const float4*)(Ab + (long long)(arow + 64) * K + k0 + ac4);
        float4 b0 = *(const float4*)(Bb + (long long)(k0 + bkr) * N + bc4);
        float4 b1 = *(const float4*)(Bb + (long long)(k0 + bkr + 8) * N + bc4);
        __syncthreads();
        Ast[(ac4 + 0) * 132 + arow] = a0.x;
        Ast[(ac4 + 1) * 132 + arow] = a0.y;
        Ast[(ac4 + 2) * 132 + arow] = a0.z;
        Ast[(ac4 + 3) * 132 + arow] = a0.w;
        Ast[(ac4 + 0) * 132 + arow + 64] = a1.x;
        Ast[(ac4 + 1) * 132 + arow + 64] = a1.y;
        Ast[(ac4 + 2) * 132 + arow + 64] = a1.z;
        Ast[(ac4 + 3) * 132 + arow + 64] = a1.w;
        *(float4*)(Bs + bkr * 128 + bc4) = b0;
        *(float4*)(Bs + (bkr + 8) * 128 + bc4) = b1;
        __syncthreads();
#pragma unroll
        for (int kk = 0; kk < 16; kk++) {
            float4 av0 = *(const float4*)(Ast + kk * 132 + ty * 8);
            float4 av1 = *(const float4*)(Ast + kk * 132 + ty * 8 + 4);
            float a[8] = {av0.x, av0.y, av0.z, av0.w, av1.x, av1.y, av1.z, av1.w};
            float b[8];
#pragma unroll
            for (int j = 0; j < 8; j++) b[j] = Bs[kk * 128 + j * 16 + tx];
#pragma unroll
            for (int i = 0; i < 8; i++)
#pragma unroll
                for (int j = 0; j < 8; j++) acc[i][j] += a[i] * b[j];
        }
    }
#pragma unroll
    for (int i = 0; i < 8; i++) {
        long long r = bm * 128 + ty * 8 + i;
#pragma unroll
        for (int j = 0; j < 8; j++) {
            int c = bn * 128 + j * 16 + tx;
            float v = accScale * acc[i][j];
            if (Res)  v += resScale * Res[r * N + c];
            if (bias) v += bias[c];
            if (act == 1) v = fmaxf(v, 0.f);
            else if (act == 2) v = (v >= 0.f) ? v : 0.01f * v;
            C[r * N + c] = v;
        }
    }
}

// ---------------- union CSR rowcount + per-e CSC colcount + degsum ----------------
__global__ void rowcnt_ext(const float* __restrict__ A, int* __restrict__ cnt,
                           float* __restrict__ dis, int* __restrict__ ccnt,
                           float* __restrict__ degsum) {
    int i = blockIdx.x;
    int tid = threadIdx.x;                 // 256
    int c = 0;
    for (int j = tid; j < N_NODES; j += 256) {
        const float* ap = A + ((long long)i * N_NODES + j) * E_TYPES;
        float a[E_TYPES];
#pragma unroll
        for (int e = 0; e < E_TYPES; e++) a[e] = ap[e];
        bool nz = (j == i);
#pragma unroll
        for (int e = 0; e < E_TYPES; e++) nz |= (a[e] != 0.f);
        c += nz ? 1 : 0;
        if (j != i) {
#pragma unroll
            for (int e = 0; e < E_TYPES; e++) {
                if (a[e] != 0.f) {
                    atomicAdd(&ccnt[e * N_NODES + j], 1);
                    atomicAdd(&degsum[e * N_NODES + j], a[e]);
                }
            }
        }
    }
    __shared__ int red[256];
    red[tid] = c;
    __syncthreads();
    for (int o = 128; o; o >>= 1) {
        if (tid < o) red[tid] += red[tid + o];
        __syncthreads();
    }
    if (tid == 0) {
        cnt[i] = red[0];
        dis[i] = rsqrtf((float)red[0]);
    }
}

// one block per scan segment of 4096 ints
__global__ void scan_kernel(const int* __restrict__ cnt_base, int* __restrict__ rp_base,
                            int seg_in, int seg_out) {
    const int* cnt = cnt_base + (long long)blockIdx.x * seg_in;
    int* rowptr = rp_base + (long long)blockIdx.x * seg_out;
    __shared__ int warpsum[32];
    int t = threadIdx.x;                   // 1024, 4 elems each
    int v[4], s = 0;
#pragma unroll
    for (int j = 0; j < 4; j++) { v[j] = cnt[t * 4 + j]; s += v[j]; }
    int lane = t & 31, warp = t >> 5;
    int x = s;
#pragma unroll
    for (int o = 1; o < 32; o <<= 1) {
        int y = __shfl_up_sync(0xffffffffu, x, o);
        if (lane >= o) x += y;
    }
    if (lane == 31) warpsum[warp] = x;
    __syncthreads();
    if (warp == 0) {
        int w = warpsum[lane];
#pragma unroll
        for (int o = 1; o < 32; o <<= 1) {
            int y = __shfl_up_sync(0xffffffffu, w, o);
            if (lane >= o) w += y;
        }
        warpsum[lane] = w;
    }
    __syncthreads();
    int excl = x - s + (warp ? warpsum[warp - 1] : 0);
    int run = excl;
    if (t == 0) rowptr[0] = 0;
#pragma unroll
    for (int j = 0; j < 4; j++) { run += v[j]; rowptr[t * 4 + j + 1] = run; }
}

// ---------------- union CSR fill + per-e CSC fill ----------------
__global__ void fill_ext(const float* __restrict__ A, const int* __restrict__ rowptr,
                         const float* __restrict__ dis, int* __restrict__ col,
                         float* __restrict__ val, const int* __restrict__ cptr,
                         int* __restrict__ cfill, int* __restrict__ csrc,
                         float* __restrict__ cval) {
    int i = blockIdx.x;
    float di = dis[i];
    __shared__ int warpCnt[8];
    __shared__ int blockBase;
    if (threadIdx.x == 0) blockBase = rowptr[i];
    __syncthreads();
    for (int j0 = 0; j0 < N_NODES; j0 += 256) {
        int j = j0 + threadIdx.x;
        const float* ap = A + ((long long)i * N_NODES + j) * E_TYPES;
        float a[E_TYPES];
#pragma unroll
        for (int e = 0; e < E_TYPES; e++) a[e] = ap[e];
        bool nz = (j == i);
#pragma unroll
        for (int e = 0; e < E_TYPES; e++) nz |= (a[e] != 0.f);
        if (j != i) {
#pragma unroll
            for (int e = 0; e < E_TYPES; e++) {
                if (a[e] != 0.f) {
                    int slot = atomicAdd(&cfill[e * N_NODES + j], 1);
                    int pos = cptr[e * (N_NODES + 1) + j] + slot;
                    csrc[e * CAPE + pos] = i;
                    cval[e * CAPE + pos] = a[e];
                }
            }
        }
        unsigned mask = __ballot_sync(0xffffffffu, nz);
        int warp = threadIdx.x >> 5, lane = threadIdx.x & 31;
        if (lane == 0) warpCnt[warp] = __popc(mask);
        __syncthreads();
        int woff = 0;
        for (int w = 0; w < warp; w++) woff += warpCnt[w];
        int total = 0;
        for (int w = 0; w < 8; w++) total += warpCnt[w];
        if (nz) {
            int pos = blockBase + woff + __popc(mask & ((1u << lane) - 1));
            col[pos] = j;
            val[pos] = di * dis[j];
        }
        __syncthreads();
        if (threadIdx.x == 0) blockBase += total;
        __syncthreads();
    }
}

// ---------------- lgcn via per-e CSC gather ----------------
__global__ void lgcn_csc(const float* __restrict__ Xw, const int* __restrict__ csrc,
                         const float* __restrict__ cval, const int* __restrict__ cptr,
                         const float* __restrict__ degsum, float* __restrict__ lgcn) {
    int n = blockIdx.x, e = blockIdx.y, d = threadIdx.x;  // 128
    int s = cptr[e * (N_NODES + 1) + n], en = cptr[e * (N_NODES + 1) + n + 1];
    const int* cs = csrc + (long long)e * CAPE;
    const float* cv = cval + (long long)e * CAPE;
    float acc = Xw[(long long)n * W_OUT + d];
    for (int k = s; k < en; k++)
        acc += cv[k] * Xw[(long long)cs[k] * W_OUT + d];
    float dv = 1.f / (1.f + degsum[e * N_NODES + n]);
    lgcn[((long long)e * N_NODES + n) * W_OUT + d] = fmaxf(acc * dv, 0.f);
}

// ---------------- attention: two-stage ----------------
__global__ void att1(const float* __restrict__ lgcn, const float* __restrict__ attw,
                     float* __restrict__ attpart) {
    int g = blockIdx.x, e = blockIdx.y, d = threadIdx.x;  // 128
    float s = 0.f;
    int n0 = g * 128;
    for (int n = n0; n < n0 + 128; n++)
        s += attw[n] * lgcn[((long long)e * N_NODES + n) * W_OUT + d];
    attpart[(e * 32 + g) * W_OUT + d] = s;
}

__global__ void att2(const float* __restrict__ attpart, const float* __restrict__ attb,
                     const float* __restrict__ attq, float* __restrict__ beta) {
    __shared__ float red[128];
    __shared__ float w[E_TYPES];
    int d = threadIdx.x;  // 128
    for (int e = 0; e < E_TYPES; e++) {
        float tot = 0.f;
#pragma unroll
        for (int g = 0; g < 32; g++) tot += attpart[(e * 32 + g) * W_OUT + d];
        red[d] = tanhf(tot + attb[d]) * attq[d];
        __syncthreads();
        for (int o = 64; o; o >>= 1) {
            if (d < o) red[d] += red[d + o];
            __syncthreads();
        }
        if (d == 0) w[e] = red[0];
        __syncthreads();
    }
    if (d == 0) {
        float mx = w[0];
        for (int e = 1; e < E_TYPES; e++) mx = fmaxf(mx, w[e]);
        float ex[E_TYPES], s = 0.f;
        for (int e = 0; e < E_TYPES; e++) { ex[e] = expf(w[e] - mx); s += ex[e]; }
        for (int e = 0; e < E_TYPES; e++) beta[e] = (float)E_TYPES * ex[e] / s;
    }
}

// ---------------- X_ = [beta*lgcn (e-major) | X] ----------------
__global__ void xcat_kernel(const float* __restrict__ lgcn, const float* __restrict__ X,
                            const float* __restrict__ beta, float* __restrict__ Xcat) {
    long long idx = (long long)blockIdx.x * 256 + threadIdx.x;
    long long total = (long long)N_NODES * H0;
    if (idx >= total) return;
    int n = (int)(idx / H0), c = (int)(idx % H0);
    float v;
    if (c < E_TYPES * W_OUT) {
        int e = c >> 7, d = c & 127;
        v = beta[e] * lgcn[((long long)e * N_NODES + n) * W_OUT + d];
    } else {
        v = X[(long long)n * W_IN + (c - E_TYPES * W_OUT)];
    }
    Xcat[idx] = v;
}

// ---------------- fp32 -> fp16 convert ----------------
__global__ void f2h_kernel(const float* __restrict__ src, __half* __restrict__ dst, int n4) {
    int i = blockIdx.x * 256 + threadIdx.x;
    if (i >= n4) return;
    float4 v = ((const float4*)src)[i];
    __half2 h0 = __floats2half2_rn(v.x, v.y);
    __half2 h1 = __floats2half2_rn(v.z, v.w);
    ((float2*)dst)[i] = make_float2(h2_as_f(h0), h2_as_f(h1));
}

// ---------------- fused GCNII layer ----------------
// block: 32 rows, 256 threads (8 warps, warp w handles rows w, w+8, w+16, w+24)
// phase1: h = 0.9 * A_hat_rows @ xh(fp16) + 0.1 * x0   -> smem hs[32][129]
// phase2: out = relu((1-bl)*h + bl*(h @ Wl))           -> xf (fp32) + xh_out (fp16)
__global__ __launch_bounds__(256, 4) void layer_fused(
    const int* __restrict__ rowptr, const int* __restrict__ colp,
    const float* __restrict__ valp, const __half* __restrict__ xh,
    const float* __restrict__ x0, const float* __restrict__ Wl, float bl,
    float* __restrict__ xf_out, __half* __restrict__ xh_out) {
    __shared__ float hs[32 * 129];
    __shared__ float Bs[32 * 128];
    int t = threadIdx.x;
    int warp = t >> 5, lane = t & 31;
    int r0 = blockIdx.x * 32;
    // ---- phase 1: sparse gather ----
#pragma unroll
    for (int rr = 0; rr < 4; rr++) {
        int lr = warp + rr * 8;
        int row = r0 + lr;
        int ks = rowptr[row], ke = rowptr[row + 1];
        float a0 = 0.f, a1 = 0.f, a2 = 0.f, a3 = 0.f;
#pragma unroll 4
        for (int k = ks; k < ke; k++) {
            int c = colp[k];
            float v = valp[k];
            float2 raw = ((const float2*)(xh + (long long)c * W_OUT))[lane];
            __half2 p0 = *(__half2*)&raw.x;
            __half2 p1 = *(__half2*)&raw.y;
            float2 f0 = __half22float2(p0);
            float2 f1 = __half22float2(p1);
            a0 += v * f0.x; a1 += v * f0.y; a2 += v * f1.x; a3 += v * f1.y;
        }
        const float4 xv = ((const float4*)(x0 + (long long)row * W_OUT))[lane];
        hs[lr * 129 + lane * 4 + 0] = 0.9f * a0 + 0.1f * xv.x;
        hs[lr * 129 + lane * 4 + 1] = 0.9f * a1 + 0.1f * xv.y;
        hs[lr * 129 + lane * 4 + 2] = 0.9f * a2 + 0.1f * xv.z;
        hs[lr * 129 + lane * 4 + 3] = 0.9f * a3 + 0.1f * xv.w;
    }
    // ---- phase 2: dense 32x128 @ 128x128 ----
    int tx = t & 31, ty = t >> 5;          // out cols tx*4.., rows ty*4..
    float acc[4][4];
#pragma unroll
    for (int i = 0; i < 4; i++)
#pragma unroll
        for (int j = 0; j < 4; j++) acc[i][j] = 0.f;
    for (int k0 = 0; k0 < 128; k0 += 32) {
        __syncthreads();
#pragma unroll
        for (int i = 0; i < 4; i++) {
            int idx = t + 256 * i;         // 1024 float4 = 32x128
            int br = idx >> 5, bc = (idx & 31) << 2;
            *(float4*)(Bs + br * 128 + bc) = *(const float4*)(Wl + (long long)(k0 + br) * W_OUT + bc);
        }
        __syncthreads();
#pragma unroll
        for (int kk = 0; kk < 32; kk++) {
            float a[4], b[4];
#pragma unroll
            for (int i = 0; i < 4; i++) a[i] = hs[(ty * 4 + i) * 129 + k0 + kk];
            float4 bv = *(const float4*)(Bs + kk * 128 + tx * 4);
            b[0] = bv.x; b[1] = bv.y; b[2] = bv.z; b[3] = bv.w;
#pragma unroll
            for (int i = 0; i < 4; i++)
#pragma unroll
                for (int j = 0; j < 4; j++) acc[i][j] += a[i] * b[j];
        }
    }
    float omb = 1.f - bl;
#pragma unroll
    for (int i = 0; i < 4; i++) {
        int lr = ty * 4 + i;
        long long row = r0 + lr;
        float4 o;
        float h0 = hs[lr * 129 + tx * 4 + 0];
        float h1 = hs[lr * 129 + tx * 4 + 1];
        float h2 = hs[lr * 129 + tx * 4 + 2];
        float h3 = hs[lr * 129 + tx * 4 + 3];
        o.x = fmaxf(bl * acc[i][0] + omb * h0, 0.f);
        o.y = fmaxf(bl * acc[i][1] + omb * h1, 0.f);
        o.z = fmaxf(bl * acc[i][2] + omb * h2, 0.f);
        o.w = fmaxf(bl * acc[i][3] + omb * h3, 0.f);
        *(float4*)(xf_out + row * W_OUT + tx * 4) = o;
        __half2 q0 = __floats2half2_rn(o.x, o.y);
        __half2 q1 = __floats2half2_rn(o.z, o.w);
        float2 packed = make_float2(h2_as_f(q0), h2_as_f(q1));
        *(float2*)(xh_out + row * W_OUT + tx * 4) = packed;
    }
}

// ---------------- head ----------------
__global__ void out_kernel(const float* __restrict__ Z, const int* __restrict__ tx,
                           const float* __restrict__ W2, const float* __restrict__ b2,
                           float* __restrict__ y) {
    int r = blockIdx.x;
    int t = threadIdx.x;                   // 128
    __shared__ float z[W_OUT];
    z[t] = Z[(long long)tx[r] * W_OUT + t];
    __syncthreads();
    if (t < NUM_CLASS) {
        float s = b2[t];
        for (int k = 0; k < W_OUT; k++) s += z[k] * W2[k * NUM_CLASS + t];
        y[r * NUM_CLASS + t] = s;
    }
}

__global__ void loss_kernel(const float* __restrict__ y, const int* __restrict__ target,
                            float* __restrict__ out) {
    __shared__ float red[256];
    int tid = threadIdx.x;                 // 256
    float part = 0.f;
    for (int r = tid; r < M_TGT; r += 256) {
        const float* yr = y + r * NUM_CLASS;
        float mx = yr[0];
#pragma unroll
        for (int c = 1; c < NUM_CLASS; c++) mx = fmaxf(mx, yr[c]);
        float se = 0.f;
#pragma unroll
        for (int c = 0; c < NUM_CLASS; c++) se += expf(yr[c] - mx);
        float lse = mx + logf(se);
        part += lse - yr[target[r]];
    }
    red[tid] = part;
    __syncthreads();
    for (int o = 128; o; o >>= 1) {
        if (tid < o) red[tid] += red[tid + o];
        __syncthreads();
    }
    if (tid == 0) out[0] = red[0] / (float)M_TGT;
}

// ---------------- launch ----------------
extern "C" void kernel_launch(void* const* d_in, const int* in_sizes, int n_in,
                              void* d_out, int out_size) {
    const float* A        = (const float*)d_in[0];
    const float* X        = (const float*)d_in[1];
    const int*   target_x = (const int*)d_in[2];
    const int*   target   = (const int*)d_in[3];
    const float* weight   = (const float*)d_in[4];
    const float* attw     = (const float*)d_in[5];
    const float* attb     = (const float*)d_in[6];
    const float* attq     = (const float*)d_in[7];
    const float* Wg       = (const float*)d_in[8];
    const float* bg       = (const float*)d_in[9];
    const float* W0       = (const float*)d_in[10];
    const float* b0       = (const float*)d_in[11];
    const float* Wconvs   = (const float*)d_in[12];
    const float* Wd1      = (const float*)d_in[13];
    const float* bd1      = (const float*)d_in[14];
    const float* W1       = (const float*)d_in[15];
    const float* b1       = (const float*)d_in[16];
    const float* W2       = (const float*)d_in[17];
    const float* b2       = (const float*)d_in[18];

    float *Xg, *Xw, *lgcn, *attpart, *beta, *Xcat, *x0, *xA, *xB, *Z1, *Z2, *ybuf;
    float *dis, *valp, *cvalp;
    __half *xh0, *xhA, *xhB;
    int *cnt, *rowptr, *colp, *zinit, *cptr, *csrcp;
    cudaGetSymbolAddress((void**)&Xg, g_Xg);
    cudaGetSymbolAddress((void**)&Xw, g_Xw);
    cudaGetSymbolAddress((void**)&lgcn, g_lgcn);
    cudaGetSymbolAddress((void**)&attpart, g_attpart);
    cudaGetSymbolAddress((void**)&beta, g_beta);
    cudaGetSymbolAddress((void**)&Xcat, g_Xcat);
    cudaGetSymbolAddress((void**)&x0, g_x0);
    cudaGetSymbolAddress((void**)&xA, g_xA);
    cudaGetSymbolAddress((void**)&xB, g_xB);
    cudaGetSymbolAddress((void**)&xh0, g_xh0);
    cudaGetSymbolAddress((void**)&xhA, g_xhA);
    cudaGetSymbolAddress((void**)&xhB, g_xhB);
    cudaGetSymbolAddress((void**)&Z1, g_Z1);
    cudaGetSymbolAddress((void**)&Z2, g_Z2);
    cudaGetSymbolAddress((void**)&ybuf, g_y);
    cudaGetSymbolAddress((void**)&cnt, g_cnt);
    cudaGetSymbolAddress((void**)&rowptr, g_rowptr);
    cudaGetSymbolAddress((void**)&dis, g_dis);
    cudaGetSymbolAddress((void**)&colp, g_col);
    cudaGetSymbolAddress((void**)&valp, g_val);
    cudaGetSymbolAddress((void**)&zinit, g_zinit);
    cudaGetSymbolAddress((void**)&cptr, g_cptr);
    cudaGetSymbolAddress((void**)&csrcp, g_csrc);
    cudaGetSymbolAddress((void**)&cvalp, g_cval);

    int* ccnt = zinit;
    int* cfill = zinit + E_TYPES * N_NODES;
    float* degsum = (float*)(zinit + 2 * E_TYPES * N_NODES);

    cudaMemsetAsync(zinit, 0, 3 * E_TYPES * N_NODES * sizeof(int));

    // 1) Xg = leaky(X @ Wg + bg), Xw = leaky(Xg @ weight)
    gemm128<<<dim3(W_IN / 128, N_NODES / 128), 256>>>(X, Wg, Xg, N_NODES, W_IN, W_IN,
                                                      bg, nullptr, 1.f, 0.f, 2);
    gemm128<<<dim3(1, N_NODES / 128), 256>>>(Xg, weight, Xw, N_NODES, W_OUT, W_IN,
                                             nullptr, nullptr, 1.f, 0.f, 2);
    // 2) sparse structure build (union CSR + per-e CSC)
    rowcnt_ext<<<N_NODES, 256>>>(A, cnt, dis, ccnt, degsum);
    scan_kernel<<<1, 1024>>>(cnt, rowptr, 0, 0);
    scan_kernel<<<E_TYPES, 1024>>>(ccnt, cptr, N_NODES, N_NODES + 1);
    fill_ext<<<N_NODES, 256>>>(A, rowptr, dis, colp, valp, cptr, cfill, csrcp, cvalp);
    // 3) lgcn + attention + concat
    lgcn_csc<<<dim3(N_NODES, E_TYPES), 128>>>(Xw, csrcp, cvalp, cptr, degsum, lgcn);
    att1<<<dim3(32, E_TYPES), 128>>>(lgcn, attw, attpart);
    att2<<<1, 128>>>(attpart, attb, attq, beta);
    {
        long long total = (long long)N_NODES * H0;
        xcat_kernel<<<(unsigned)((total + 255) / 256), 256>>>(lgcn, X, beta, Xcat);
    }
    gemm128<<<dim3(1, N_NODES / 128), 256>>>(Xcat, W0, x0, N_NODES, W_OUT, H0,
                                             b0, nullptr, 1.f, 0.f, 1);
    f2h_kernel<<<(N_NODES * W_OUT / 4 + 255) / 256, 256>>>(x0, xh0, N_NODES * W_OUT / 4);
    // 4) 64 fused GCNII layers
    const __half* xhin = xh0;
    float* fbufs[2] = {xA, xB};
    __half* hbufs[2] = {xhA, xhB};
    const float* xin = x0;
    for (int l = 0; l < NUM_LAYERS; l++) {
        float bl = logf(0.5f / (float)(l + 1) + 1.f);
        float* xf = fbufs[l & 1];
        __half* xh = hbufs[l & 1];
        layer_fused<<<N_NODES / 32, 256>>>(rowptr, colp, valp, xhin, x0,
                                           Wconvs + (long long)l * W_OUT * W_OUT, bl, xf, xh);
        xhin = xh;
        xin = xf;
    }
    // 5) head
    gemm128<<<dim3(1, N_NODES / 128), 256>>>(xin, Wd1, Z1, N_NODES, W_OUT, W_OUT,
                                             bd1, nullptr, 1.f, 0.f, 2);
    gemm128<<<dim3(1, N_NODES / 128), 256>>>(Z1, W1, Z2, N_NODES, W_OUT, W_OUT,
                                             b1, nullptr, 1.f, 0.f, 2);
    float* yout;
    bool with_loss;
    if (out_size >= M_TGT * NUM_CLASS + 1) { yout = (float*)d_out + 1; with_loss = true; }
    else if (out_size == M_TGT * NUM_CLASS) { yout = (float*)d_out; with_loss = false; }
    else { yout = ybuf; with_loss = true; }
    out_kernel<<<M_TGT, 128>>>(Z2, target_x, W2, b2, yout);
    if (with_loss) loss_kernel<<<1, 256>>>(yout, target, (float*)d_out);
}

// round 5
// speedup vs baseline: 3.1946x; 1.9020x over previous
#include <cuda_runtime.h>
#include <cuda_fp16.h>
#include <math.h>

#define N_NODES 4096
#define E_TYPES 5
#define W_IN 512
#define W_OUT 128
#define NUM_CLASS 16
#define M_TGT 1024
#define NUM_LAYERS 64
#define H0 (W_IN + E_TYPES * W_OUT)   // 1152
#define NNZ_CAP 2097152
#define CAPE 262144                   // per-edge-type CSC capacity
#define ATT_G 128

// ---------------- static scratch ----------------
__device__ float g_Xg[N_NODES * W_IN];
__device__ float g_Xw[N_NODES * W_OUT];
__device__ float g_lgcn[E_TYPES * N_NODES * W_OUT];
__device__ float g_attpart[E_TYPES * ATT_G * W_OUT];
__device__ float g_beta[E_TYPES];
__device__ float g_Xcat[N_NODES * H0];
__device__ float g_x0[N_NODES * W_OUT];
__device__ float g_xlast[N_NODES * W_OUT];
__device__ __half g_xh0[N_NODES * W_OUT];
__device__ __half g_xhA[N_NODES * W_OUT];
__device__ __half g_xhB[N_NODES * W_OUT];
__device__ float g_Z1[N_NODES * W_OUT];
__device__ float g_Z2[N_NODES * W_OUT];
__device__ float g_y[M_TGT * NUM_CLASS];
__device__ int   g_cnt[N_NODES];
__device__ int   g_rowptr[N_NODES + 1];
__device__ float g_dis[N_NODES];
__device__ int   g_col[NNZ_CAP];
__device__ float g_val[NNZ_CAP];
__device__ int   g_zinit[3 * E_TYPES * N_NODES];    // ccnt | cfill | degsum(float)
__device__ int   g_cptr[E_TYPES * (N_NODES + 1)];
__device__ int   g_csrc[E_TYPES * CAPE];
__device__ float g_cval[E_TYPES * CAPE];

__device__ __forceinline__ float h2_as_f(__half2 h) {
    return __uint_as_float(*(unsigned*)&h);
}

// ---------------- 128x128x16 register-tiled GEMM ----------------
// C[M,N] = act(accScale*(A@B) + resScale*Res + bias), act: 0 none, 1 relu, 2 leaky
__global__ __launch_bounds__(256, 2) void gemm128(
    const float* __restrict__ A, const float* __restrict__ B, float* __restrict__ C,
    int M, int N, int K, const float* __restrict__ bias, const float* __restrict__ Res,
    float accScale, float resScale, int act) {
    __shared__ float Ast[16 * 132];
    __shared__ float Bs[16 * 128];
    int bm = blockIdx.y, bn = blockIdx.x;
    int t = threadIdx.x;
    int tx = t & 15, ty = t >> 4;
    int arow = t >> 2, ac4 = (t & 3) << 2;
    int bkr = t >> 5, bc4 = (t & 31) << 2;
    float acc[8][8];
#pragma unroll
    for (int i = 0; i < 8; i++)
#pragma unroll
        for (int j = 0; j < 8; j++) acc[i][j] = 0.f;
    const float* Ab = A + (long long)(bm * 128) * K;
    const float* Bb = B + bn * 128;
    for (int k0 = 0; k0 < K; k0 += 16) {
        float4 a0 = *(const float4*)(Ab + (long long)arow * K + k0 + ac4);
        float4 a1 = *(const float4*)(Ab + (long long)(arow + 64) * K + k0 + ac4);
        float4 b0 = *(const float4*)(Bb + (long long)(k0 + bkr) * N + bc4);
        float4 b1 = *(const float4*)(Bb + (long long)(k0 + bkr + 8) * N + bc4);
        __syncthreads();
        Ast[(ac4 + 0) * 132 + arow] = a0.x;
        Ast[(ac4 + 1) * 132 + arow] = a0.y;
        Ast[(ac4 + 2) * 132 + arow] = a0.z;
        Ast[(ac4 + 3) * 132 + arow] = a0.w;
        Ast[(ac4 + 0) * 132 + arow + 64] = a1.x;
        Ast[(ac4 + 1) * 132 + arow + 64] = a1.y;
        Ast[(ac4 + 2) * 132 + arow + 64] = a1.z;
        Ast[(ac4 + 3) * 132 + arow + 64] = a1.w;
        *(float4*)(Bs + bkr * 128 + bc4) = b0;
        *(float4*)(Bs + (bkr + 8) * 128 + bc4) = b1;
        __syncthreads();
#pragma unroll
        for (int kk = 0; kk < 16; kk++) {
            float4 av0 = *(const float4*)(Ast + kk * 132 + ty * 8);
            float4 av1 = *(const float4*)(Ast + kk * 132 + ty * 8 + 4);
            float a[8] = {av0.x, av0.y, av0.z, av0.w, av1.x, av1.y, av1.z, av1.w};
            float b[8];
#pragma unroll
            for (int j = 0; j < 8; j++) b[j] = Bs[kk * 128 + j * 16 + tx];
#pragma unroll
            for (int i = 0; i < 8; i++)
#pragma unroll
                for (int j = 0; j < 8; j++) acc[i][j] += a[i] * b[j];
        }
    }
#pragma unroll
    for (int i = 0; i < 8; i++) {
        long long r = bm * 128 + ty * 8 + i;
#pragma unroll
        for (int j = 0; j < 8; j++) {
            int c = bn * 128 + j * 16 + tx;
            float v = accScale * acc[i][j];
            if (Res)  v += resScale * Res[r * N + c];
            if (bias) v += bias[c];
            if (act == 1) v = fmaxf(v, 0.f);
            else if (act == 2) v = (v >= 0.f) ? v : 0.01f * v;
            C[r * N + c] = v;
        }
    }
}

// ---------------- union CSR rowcount + per-e CSC colcount + degsum ----------------
__global__ void rowcnt_ext(const float* __restrict__ A, int* __restrict__ cnt,
                           float* __restrict__ dis, int* __restrict__ ccnt,
                           float* __restrict__ degsum) {
    int i = blockIdx.x;
    int tid = threadIdx.x;                 // 256
    int c = 0;
    for (int j = tid; j < N_NODES; j += 256) {
        const float* ap = A + ((long long)i * N_NODES + j) * E_TYPES;
        float a[E_TYPES];
#pragma unroll
        for (int e = 0; e < E_TYPES; e++) a[e] = ap[e];
        bool nz = (j == i);
#pragma unroll
        for (int e = 0; e < E_TYPES; e++) nz |= (a[e] != 0.f);
        c += nz ? 1 : 0;
        if (j != i) {
#pragma unroll
            for (int e = 0; e < E_TYPES; e++) {
                if (a[e] != 0.f) {
                    atomicAdd(&ccnt[e * N_NODES + j], 1);
                    atomicAdd(&degsum[e * N_NODES + j], a[e]);
                }
            }
        }
    }
    __shared__ int red[256];
    red[tid] = c;
    __syncthreads();
    for (int o = 128; o; o >>= 1) {
        if (tid < o) red[tid] += red[tid + o];
        __syncthreads();
    }
    if (tid == 0) {
        cnt[i] = red[0];
        dis[i] = rsqrtf((float)red[0]);
    }
}

// one block per scan segment of 4096 ints
__global__ void scan_kernel(const int* __restrict__ cnt_base, int* __restrict__ rp_base,
                            int seg_in, int seg_out) {
    const int* cnt = cnt_base + (long long)blockIdx.x * seg_in;
    int* rowptr = rp_base + (long long)blockIdx.x * seg_out;
    __shared__ int warpsum[32];
    int t = threadIdx.x;                   // 1024, 4 elems each
    int v[4], s = 0;
#pragma unroll
    for (int j = 0; j < 4; j++) { v[j] = cnt[t * 4 + j]; s += v[j]; }
    int lane = t & 31, warp = t >> 5;
    int x = s;
#pragma unroll
    for (int o = 1; o < 32; o <<= 1) {
        int y = __shfl_up_sync(0xffffffffu, x, o);
        if (lane >= o) x += y;
    }
    if (lane == 31) warpsum[warp] = x;
    __syncthreads();
    if (warp == 0) {
        int w = warpsum[lane];
#pragma unroll
        for (int o = 1; o < 32; o <<= 1) {
            int y = __shfl_up_sync(0xffffffffu, w, o);
            if (lane >= o) w += y;
        }
        warpsum[lane] = w;
    }
    __syncthreads();
    int excl = x - s + (warp ? warpsum[warp - 1] : 0);
    int run = excl;
    if (t == 0) rowptr[0] = 0;
#pragma unroll
    for (int j = 0; j < 4; j++) { run += v[j]; rowptr[t * 4 + j + 1] = run; }
}

// ---------------- union CSR fill + per-e CSC fill ----------------
__global__ void fill_ext(const float* __restrict__ A, const int* __restrict__ rowptr,
                         const float* __restrict__ dis, int* __restrict__ col,
                         float* __restrict__ val, const int* __restrict__ cptr,
                         int* __restrict__ cfill, int* __restrict__ csrc,
                         float* __restrict__ cval) {
    int i = blockIdx.x;
    float di = dis[i];
    __shared__ int warpCnt[8];
    __shared__ int blockBase;
    if (threadIdx.x == 0) blockBase = rowptr[i];
    __syncthreads();
    for (int j0 = 0; j0 < N_NODES; j0 += 256) {
        int j = j0 + threadIdx.x;
        const float* ap = A + ((long long)i * N_NODES + j) * E_TYPES;
        float a[E_TYPES];
#pragma unroll
        for (int e = 0; e < E_TYPES; e++) a[e] = ap[e];
        bool nz = (j == i);
#pragma unroll
        for (int e = 0; e < E_TYPES; e++) nz |= (a[e] != 0.f);
        if (j != i) {
#pragma unroll
            for (int e = 0; e < E_TYPES; e++) {
                if (a[e] != 0.f) {
                    int slot = atomicAdd(&cfill[e * N_NODES + j], 1);
                    int pos = cptr[e * (N_NODES + 1) + j] + slot;
                    csrc[e * CAPE + pos] = i;
                    cval[e * CAPE + pos] = a[e];
                }
            }
        }
        unsigned mask = __ballot_sync(0xffffffffu, nz);
        int warp = threadIdx.x >> 5, lane = threadIdx.x & 31;
        if (lane == 0) warpCnt[warp] = __popc(mask);
        __syncthreads();
        int woff = 0;
        for (int w = 0; w < warp; w++) woff += warpCnt[w];
        int total = 0;
        for (int w = 0; w < 8; w++) total += warpCnt[w];
        if (nz) {
            int pos = blockBase + woff + __popc(mask & ((1u << lane) - 1));
            col[pos] = j;
            val[pos] = di * dis[j];
        }
        __syncthreads();
        if (threadIdx.x == 0) blockBase += total;
        __syncthreads();
    }
}

// ---------------- lgcn via per-e CSC gather ----------------
__global__ void lgcn_csc(const float* __restrict__ Xw, const int* __restrict__ csrc,
                         const float* __restrict__ cval, const int* __restrict__ cptr,
                         const float* __restrict__ degsum, float* __restrict__ lgcn) {
    int n = blockIdx.x, e = blockIdx.y, d = threadIdx.x;  // 128
    int s = cptr[e * (N_NODES + 1) + n], en = cptr[e * (N_NODES + 1) + n + 1];
    const int* cs = csrc + (long long)e * CAPE;
    const float* cv = cval + (long long)e * CAPE;
    float acc = Xw[(long long)n * W_OUT + d];
    for (int k = s; k < en; k++)
        acc += cv[k] * Xw[(long long)cs[k] * W_OUT + d];
    float dv = 1.f / (1.f + degsum[e * N_NODES + n]);
    lgcn[((long long)e * N_NODES + n) * W_OUT + d] = fmaxf(acc * dv, 0.f);
}

// ---------------- attention: two-stage ----------------
__global__ void att1(const float* __restrict__ lgcn, const float* __restrict__ attw,
                     float* __restrict__ attpart) {
    int g = blockIdx.x, e = blockIdx.y, d = threadIdx.x;  // ATT_G groups of 32
    float s = 0.f;
    int n0 = g * (N_NODES / ATT_G);
    for (int n = n0; n < n0 + N_NODES / ATT_G; n++)
        s += attw[n] * lgcn[((long long)e * N_NODES + n) * W_OUT + d];
    attpart[(e * ATT_G + g) * W_OUT + d] = s;
}

__global__ void att2(const float* __restrict__ attpart, const float* __restrict__ attb,
                     const float* __restrict__ attq, float* __restrict__ beta) {
    __shared__ float red[128];
    __shared__ float w[E_TYPES];
    int d = threadIdx.x;  // 128
    for (int e = 0; e < E_TYPES; e++) {
        float tot = 0.f;
#pragma unroll 8
        for (int g = 0; g < ATT_G; g++) tot += attpart[(e * ATT_G + g) * W_OUT + d];
        red[d] = tanhf(tot + attb[d]) * attq[d];
        __syncthreads();
        for (int o = 64; o; o >>= 1) {
            if (d < o) red[d] += red[d + o];
            __syncthreads();
        }
        if (d == 0) w[e] = red[0];
        __syncthreads();
    }
    if (d == 0) {
        float mx = w[0];
        for (int e = 1; e < E_TYPES; e++) mx = fmaxf(mx, w[e]);
        float ex[E_TYPES], s = 0.f;
        for (int e = 0; e < E_TYPES; e++) { ex[e] = expf(w[e] - mx); s += ex[e]; }
        for (int e = 0; e < E_TYPES; e++) beta[e] = (float)E_TYPES * ex[e] / s;
    }
}

// ---------------- X_ = [beta*lgcn (e-major) | X] ----------------
__global__ void xcat_kernel(const float* __restrict__ lgcn, const float* __restrict__ X,
                            const float* __restrict__ beta, float* __restrict__ Xcat) {
    long long idx = (long long)blockIdx.x * 256 + threadIdx.x;
    long long total = (long long)N_NODES * H0;
    if (idx >= total) return;
    int n = (int)(idx / H0), c = (int)(idx % H0);
    float v;
    if (c < E_TYPES * W_OUT) {
        int e = c >> 7, d = c & 127;
        v = beta[e] * lgcn[((long long)e * N_NODES + n) * W_OUT + d];
    } else {
        v = X[(long long)n * W_IN + (c - E_TYPES * W_OUT)];
    }
    Xcat[idx] = v;
}

// ---------------- fp32 -> fp16 convert ----------------
__global__ void f2h_kernel(const float* __restrict__ src, __half* __restrict__ dst, int n4) {
    int i = blockIdx.x * 256 + threadIdx.x;
    if (i >= n4) return;
    float4 v = ((const float4*)src)[i];
    __half2 h0 = __floats2half2_rn(v.x, v.y);
    __half2 h1 = __floats2half2_rn(v.z, v.w);
    ((float2*)dst)[i] = make_float2(h2_as_f(h0), h2_as_f(h1));
}

// ---------------- fused GCNII layer, 8 rows/block ----------------
// 256 threads = 8 warps; warp w owns row r0+w fully (gather + dense + epilogue).
// phase1: h = 0.9 * A_hat_row @ xh(fp16) + 0.1 * x0   (regs + hs[w][.])
// phase2: out = relu((1-bl)*h + bl*(h @ Wl))
__global__ __launch_bounds__(256) void layer_fused8(
    const int* __restrict__ rowptr, const int* __restrict__ colp,
    const float* __restrict__ valp, const __half* __restrict__ xh,
    const float* __restrict__ x0, const float* __restrict__ Wl, float bl,
    float* __restrict__ xf_out, __half* __restrict__ xh_out) {
    __shared__ float hs[8][132];
    __shared__ float Bs[32 * 128];
    int t = threadIdx.x;
    int warp = t >> 5, lane = t & 31;
    int row = blockIdx.x * 8 + warp;
    int ks = rowptr[row], ke = rowptr[row + 1];
    float a0 = 0.f, a1 = 0.f, a2 = 0.f, a3 = 0.f;
    // gather: warp-batched col/val + shfl distribute; each lane covers cols lane*4..+3
    for (int k0 = ks; k0 < ke; k0 += 32) {
        int cnt = min(32, ke - k0);
        int cR = 0; float vR = 0.f;
        if (lane < cnt) { cR = colp[k0 + lane]; vR = valp[k0 + lane]; }
#pragma unroll 4
        for (int kk = 0; kk < cnt; kk++) {
            int c = __shfl_sync(0xffffffffu, cR, kk);
            float v = __shfl_sync(0xffffffffu, vR, kk);
            float2 raw = ((const float2*)(xh + (long long)c * W_OUT))[lane];
            __half2 p0 = *(__half2*)&raw.x;
            __half2 p1 = *(__half2*)&raw.y;
            float2 f0 = __half22float2(p0);
            float2 f1 = __half22float2(p1);
            a0 += v * f0.x; a1 += v * f0.y; a2 += v * f1.x; a3 += v * f1.y;
        }
    }
    const float4 xv = ((const float4*)(x0 + (long long)row * W_OUT))[lane];
    float h0 = 0.9f * a0 + 0.1f * xv.x;
    float h1 = 0.9f * a1 + 0.1f * xv.y;
    float h2 = 0.9f * a2 + 0.1f * xv.z;
    float h3 = 0.9f * a3 + 0.1f * xv.w;
    hs[warp][lane * 4 + 0] = h0;
    hs[warp][lane * 4 + 1] = h1;
    hs[warp][lane * 4 + 2] = h2;
    hs[warp][lane * 4 + 3] = h3;
    // dense: out row = warp's row; each lane computes cols lane*4..+3
    float acc0 = 0.f, acc1 = 0.f, acc2 = 0.f, acc3 = 0.f;
    for (int k0 = 0; k0 < 128; k0 += 32) {
        __syncthreads();                   // first iter also publishes hs
#pragma unroll
        for (int i = 0; i < 4; i++) {
            int idx = t + 256 * i;         // 1024 float4 = 32x128
            int br = idx >> 5, bc = (idx & 31) << 2;
            *(float4*)(Bs + br * 128 + bc) = *(const float4*)(Wl + (long long)(k0 + br) * W_OUT + bc);
        }
        __syncthreads();
#pragma unroll
        for (int kk = 0; kk < 32; kk++) {
            float a = hs[warp][k0 + kk];
            float4 b = *(const float4*)(Bs + kk * 128 + lane * 4);
            acc0 += a * b.x; acc1 += a * b.y; acc2 += a * b.z; acc3 += a * b.w;
        }
    }
    float omb = 1.f - bl;
    float4 o;
    o.x = fmaxf(bl * acc0 + omb * h0, 0.f);
    o.y = fmaxf(bl * acc1 + omb * h1, 0.f);
    o.z = fmaxf(bl * acc2 + omb * h2, 0.f);
    o.w = fmaxf(bl * acc3 + omb * h3, 0.f);
    if (xf_out)
        *(float4*)(xf_out + (long long)row * W_OUT + lane * 4) = o;
    if (xh_out) {
        __half2 q0 = __floats2half2_rn(o.x, o.y);
        __half2 q1 = __floats2half2_rn(o.z, o.w);
        *(float2*)(xh_out + (long long)row * W_OUT + lane * 4) = make_float2(h2_as_f(q0), h2_as_f(q1));
    }
}

// ---------------- head ----------------
__global__ void out_kernel(const float* __restrict__ Z, const int* __restrict__ tx,
                           const float* __restrict__ W2, const float* __restrict__ b2,
                           float* __restrict__ y) {
    int r = blockIdx.x;
    int t = threadIdx.x;                   // 128
    __shared__ float z[W_OUT];
    z[t] = Z[(long long)tx[r] * W_OUT + t];
    __syncthreads();
    if (t < NUM_CLASS) {
        float s = b2[t];
        for (int k = 0; k < W_OUT; k++) s += z[k] * W2[k * NUM_CLASS + t];
        y[r * NUM_CLASS + t] = s;
    }
}

__global__ void loss_kernel(const float* __restrict__ y, const int* __restrict__ target,
                            float* __restrict__ out) {
    __shared__ float red[256];
    int tid = threadIdx.x;                 // 256
    float part = 0.f;
    for (int r = tid; r < M_TGT; r += 256) {
        const float* yr = y + r * NUM_CLASS;
        float mx = yr[0];
#pragma unroll
        for (int c = 1; c < NUM_CLASS; c++) mx = fmaxf(mx, yr[c]);
        float se = 0.f;
#pragma unroll
        for (int c = 0; c < NUM_CLASS; c++) se += expf(yr[c] - mx);
        float lse = mx + logf(se);
        part += lse - yr[target[r]];
    }
    red[tid] = part;
    __syncthreads();
    for (int o = 128; o; o >>= 1) {
        if (tid < o) red[tid] += red[tid + o];
        __syncthreads();
    }
    if (tid == 0) out[0] = red[0] / (float)M_TGT;
}

// ---------------- launch ----------------
extern "C" void kernel_launch(void* const* d_in, const int* in_sizes, int n_in,
                              void* d_out, int out_size) {
    const float* A        = (const float*)d_in[0];
    const float* X        = (const float*)d_in[1];
    const int*   target_x = (const int*)d_in[2];
    const int*   target   = (const int*)d_in[3];
    const float* weight   = (const float*)d_in[4];
    const float* attw     = (const float*)d_in[5];
    const float* attb     = (const float*)d_in[6];
    const float* attq     = (const float*)d_in[7];
    const float* Wg       = (const float*)d_in[8];
    const float* bg       = (const float*)d_in[9];
    const float* W0       = (const float*)d_in[10];
    const float* b0       = (const float*)d_in[11];
    const float* Wconvs   = (const float*)d_in[12];
    const float* Wd1      = (const float*)d_in[13];
    const float* bd1      = (const float*)d_in[14];
    const float* W1       = (const float*)d_in[15];
    const float* b1       = (const float*)d_in[16];
    const float* W2       = (const float*)d_in[17];
    const float* b2       = (const float*)d_in[18];

    float *Xg, *Xw, *lgcn, *attpart, *beta, *Xcat, *x0, *xlast, *Z1, *Z2, *ybuf;
    float *dis, *valp, *cvalp;
    __half *xh0, *xhA, *xhB;
    int *cnt, *rowptr, *colp, *zinit, *cptr, *csrcp;
    cudaGetSymbolAddress((void**)&Xg, g_Xg);
    cudaGetSymbolAddress((void**)&Xw, g_Xw);
    cudaGetSymbolAddress((void**)&lgcn, g_lgcn);
    cudaGetSymbolAddress((void**)&attpart, g_attpart);
    cudaGetSymbolAddress((void**)&beta, g_beta);
    cudaGetSymbolAddress((void**)&Xcat, g_Xcat);
    cudaGetSymbolAddress((void**)&x0, g_x0);
    cudaGetSymbolAddress((void**)&xlast, g_xlast);
    cudaGetSymbolAddress((void**)&xh0, g_xh0);
    cudaGetSymbolAddress((void**)&xhA, g_xhA);
    cudaGetSymbolAddress((void**)&xhB, g_xhB);
    cudaGetSymbolAddress((void**)&Z1, g_Z1);
    cudaGetSymbolAddress((void**)&Z2, g_Z2);
    cudaGetSymbolAddress((void**)&ybuf, g_y);
    cudaGetSymbolAddress((void**)&cnt, g_cnt);
    cudaGetSymbolAddress((void**)&rowptr, g_rowptr);
    cudaGetSymbolAddress((void**)&dis, g_dis);
    cudaGetSymbolAddress((void**)&colp, g_col);
    cudaGetSymbolAddress((void**)&valp, g_val);
    cudaGetSymbolAddress((void**)&zinit, g_zinit);
    cudaGetSymbolAddress((void**)&cptr, g_cptr);
    cudaGetSymbolAddress((void**)&csrcp, g_csrc);
    cudaGetSymbolAddress((void**)&cvalp, g_cval);

    int* ccnt = zinit;
    int* cfill = zinit + E_TYPES * N_NODES;
    float* degsum = (float*)(zinit + 2 * E_TYPES * N_NODES);

    cudaMemsetAsync(zinit, 0, 3 * E_TYPES * N_NODES * sizeof(int));

    // 1) Xg = leaky(X @ Wg + bg), Xw = leaky(Xg @ weight)
    gemm128<<<dim3(W_IN / 128, N_NODES / 128), 256>>>(X, Wg, Xg, N_NODES, W_IN, W_IN,
                                                      bg, nullptr, 1.f, 0.f, 2);
    gemm128<<<dim3(1, N_NODES / 128), 256>>>(Xg, weight, Xw, N_NODES, W_OUT, W_IN,
                                             nullptr, nullptr, 1.f, 0.f, 2);
    // 2) sparse structure build (union CSR + per-e CSC)
    rowcnt_ext<<<N_NODES, 256>>>(A, cnt, dis, ccnt, degsum);
    scan_kernel<<<1, 1024>>>(cnt, rowptr, 0, 0);
    scan_kernel<<<E_TYPES, 1024>>>(ccnt, cptr, N_NODES, N_NODES + 1);
    fill_ext<<<N_NODES, 256>>>(A, rowptr, dis, colp, valp, cptr, cfill, csrcp, cvalp);
    // 3) lgcn + attention + concat
    lgcn_csc<<<dim3(N_NODES, E_TYPES), 128>>>(Xw, csrcp, cvalp, cptr, degsum, lgcn);
    att1<<<dim3(ATT_G, E_TYPES), 128>>>(lgcn, attw, attpart);
    att2<<<1, 128>>>(attpart, attb, attq, beta);
    {
        long long total = (long long)N_NODES * H0;
        xcat_kernel<<<(unsigned)((total + 255) / 256), 256>>>(lgcn, X, beta, Xcat);
    }
    gemm128<<<dim3(1, N_NODES / 128), 256>>>(Xcat, W0, x0, N_NODES, W_OUT, H0,
                                             b0, nullptr, 1.f, 0.f, 1);
    f2h_kernel<<<(N_NODES * W_OUT / 4 + 255) / 256, 256>>>(x0, xh0, N_NODES * W_OUT / 4);
    // 4) 64 fused GCNII layers (fp16 activation carry; fp32 emitted on last layer only)
    const __half* xhin = xh0;
    __half* hbufs[2] = {xhA, xhB};
    for (int l = 0; l < NUM_LAYERS; l++) {
        float bl = logf(0.5f / (float)(l + 1) + 1.f);
        bool last = (l == NUM_LAYERS - 1);
        __half* xh = hbufs[l & 1];
        layer_fused8<<<N_NODES / 8, 256>>>(rowptr, colp, valp, xhin, x0,
                                           Wconvs + (long long)l * W_OUT * W_OUT, bl,
                                           last ? xlast : nullptr,
                                           last ? nullptr : xh);
        xhin = xh;
    }
    // 5) head
    gemm128<<<dim3(1, N_NODES / 128), 256>>>(xlast, Wd1, Z1, N_NODES, W_OUT, W_OUT,
                                             bd1, nullptr, 1.f, 0.f, 2);
    gemm128<<<dim3(1, N_NODES / 128), 256>>>(Z1, W1, Z2, N_NODES, W_OUT, W_OUT,
                                             b1, nullptr, 1.f, 0.f, 2);
    float* yout;
    bool with_loss;
    if (out_size >= M_TGT * NUM_CLASS + 1) { yout = (float*)d_out + 1; with_loss = true; }
    else if (out_size == M_TGT * NUM_CLASS) { yout = (float*)d_out; with_loss = false; }
    else { yout = ybuf; with_loss = true; }
    out_kernel<<<M_TGT, 128>>>(Z2, target_x, W2, b2, yout);
    if (with_loss) loss_kernel<<<1, 256>>>(yout, target, (float*)d_out);
}

// round 6
// speedup vs baseline: 3.2336x; 1.0122x over previous
#include <cuda_runtime.h>
#include <cuda_fp16.h>
#include <math.h>

#define N_NODES 4096
#define E_TYPES 5
#define W_IN 512
#define W_OUT 128
#define NUM_CLASS 16
#define M_TGT 1024
#define NUM_LAYERS 64
#define H0 (W_IN + E_TYPES * W_OUT)   // 1152
#define NNZ_CAP 2097152
#define CAPE 262144                   // per-edge-type CSC capacity
#define ATT_G 128

// ---------------- static scratch ----------------
__device__ float g_Xg[N_NODES * W_IN];
__device__ float g_Xw[N_NODES * W_OUT];
__device__ float g_lgcn[E_TYPES * N_NODES * W_OUT];
__device__ float g_attpart[E_TYPES * ATT_G * W_OUT];
__device__ float g_beta[E_TYPES];
__device__ float g_Xcat[N_NODES * H0];
__device__ float g_x0[N_NODES * W_OUT];
__device__ float g_xlast[N_NODES * W_OUT];
__device__ __half g_xh0[N_NODES * W_OUT];
__device__ __half g_xhA[N_NODES * W_OUT];
__device__ __half g_xhB[N_NODES * W_OUT];
__device__ float g_Z1[N_NODES * W_OUT];
__device__ float g_Z2[N_NODES * W_OUT];
__device__ float g_y[M_TGT * NUM_CLASS];
__device__ int   g_cnt[N_NODES];
__device__ int   g_rowptr[N_NODES + 1];
__device__ float g_dis[N_NODES];
__device__ int   g_col[NNZ_CAP];
__device__ float g_val[NNZ_CAP];
__device__ int   g_zinit[3 * E_TYPES * N_NODES];    // ccnt | cfill | degsum(float)
__device__ int   g_cptr[E_TYPES * (N_NODES + 1)];
__device__ int   g_csrc[E_TYPES * CAPE];
__device__ float g_cval[E_TYPES * CAPE];

__device__ __forceinline__ float h2_as_f(__half2 h) {
    return __uint_as_float(*(unsigned*)&h);
}

// ---------------- 128x128x16 register-tiled GEMM ----------------
// C[M,N] = act(accScale*(A@B) + resScale*Res + bias), act: 0 none, 1 relu, 2 leaky
__global__ __launch_bounds__(256, 2) void gemm128(
    const float* __restrict__ A, const float* __restrict__ B, float* __restrict__ C,
    int M, int N, int K, const float* __restrict__ bias, const float* __restrict__ Res,
    float accScale, float resScale, int act) {
    __shared__ float Ast[16 * 132];
    __shared__ float Bs[16 * 128];
    int bm = blockIdx.y, bn = blockIdx.x;
    int t = threadIdx.x;
    int tx = t & 15, ty = t >> 4;
    int arow = t >> 2, ac4 = (t & 3) << 2;
    int bkr = t >> 5, bc4 = (t & 31) << 2;
    float acc[8][8];
#pragma unroll
    for (int i = 0; i < 8; i++)
#pragma unroll
        for (int j = 0; j < 8; j++) acc[i][j] = 0.f;
    const float* Ab = A + (long long)(bm * 128) * K;
    const float* Bb = B + bn * 128;
    for (int k0 = 0; k0 < K; k0 += 16) {
        float4 a0 = *(const float4*)(Ab + (long long)arow * K + k0 + ac4);
        float4 a1 = *(const float4*)(Ab + (long long)(arow + 64) * K + k0 + ac4);
        float4 b0 = *(const float4*)(Bb + (long long)(k0 + bkr) * N + bc4);
        float4 b1 = *(const float4*)(Bb + (long long)(k0 + bkr + 8) * N + bc4);
        __syncthreads();
        Ast[(ac4 + 0) * 132 + arow] = a0.x;
        Ast[(ac4 + 1) * 132 + arow] = a0.y;
        Ast[(ac4 + 2) * 132 + arow] = a0.z;
        Ast[(ac4 + 3) * 132 + arow] = a0.w;
        Ast[(ac4 + 0) * 132 + arow + 64] = a1.x;
        Ast[(ac4 + 1) * 132 + arow + 64] = a1.y;
        Ast[(ac4 + 2) * 132 + arow + 64] = a1.z;
        Ast[(ac4 + 3) * 132 + arow + 64] = a1.w;
        *(float4*)(Bs + bkr * 128 + bc4) = b0;
        *(float4*)(Bs + (bkr + 8) * 128 + bc4) = b1;
        __syncthreads();
#pragma unroll
        for (int kk = 0; kk < 16; kk++) {
            float4 av0 = *(const float4*)(Ast + kk * 132 + ty * 8);
            float4 av1 = *(const float4*)(Ast + kk * 132 + ty * 8 + 4);
            float a[8] = {av0.x, av0.y, av0.z, av0.w, av1.x, av1.y, av1.z, av1.w};
            float b[8];
#pragma unroll
            for (int j = 0; j < 8; j++) b[j] = Bs[kk * 128 + j * 16 + tx];
#pragma unroll
            for (int i = 0; i < 8; i++)
#pragma unroll
                for (int j = 0; j < 8; j++) acc[i][j] += a[i] * b[j];
        }
    }
#pragma unroll
    for (int i = 0; i < 8; i++) {
        long long r = bm * 128 + ty * 8 + i;
#pragma unroll
        for (int j = 0; j < 8; j++) {
            int c = bn * 128 + j * 16 + tx;
            float v = accScale * acc[i][j];
            if (Res)  v += resScale * Res[r * N + c];
            if (bias) v += bias[c];
            if (act == 1) v = fmaxf(v, 0.f);
            else if (act == 2) v = (v >= 0.f) ? v : 0.01f * v;
            C[r * N + c] = v;
        }
    }
}

// ---------------- union CSR rowcount + per-e CSC colcount + degsum ----------------
__global__ void rowcnt_ext(const float* __restrict__ A, int* __restrict__ cnt,
                           float* __restrict__ dis, int* __restrict__ ccnt,
                           float* __restrict__ degsum) {
    int i = blockIdx.x;
    int tid = threadIdx.x;                 // 256
    int c = 0;
    for (int j = tid; j < N_NODES; j += 256) {
        const float* ap = A + ((long long)i * N_NODES + j) * E_TYPES;
        float a[E_TYPES];
#pragma unroll
        for (int e = 0; e < E_TYPES; e++) a[e] = ap[e];
        bool nz = (j == i);
#pragma unroll
        for (int e = 0; e < E_TYPES; e++) nz |= (a[e] != 0.f);
        c += nz ? 1 : 0;
        if (j != i) {
#pragma unroll
            for (int e = 0; e < E_TYPES; e++) {
                if (a[e] != 0.f) {
                    atomicAdd(&ccnt[e * N_NODES + j], 1);
                    atomicAdd(&degsum[e * N_NODES + j], a[e]);
                }
            }
        }
    }
    __shared__ int red[256];
    red[tid] = c;
    __syncthreads();
    for (int o = 128; o; o >>= 1) {
        if (tid < o) red[tid] += red[tid + o];
        __syncthreads();
    }
    if (tid == 0) {
        cnt[i] = red[0];
        dis[i] = rsqrtf((float)red[0]);
    }
}

// one block per scan segment of 4096 ints
__global__ void scan_kernel(const int* __restrict__ cnt_base, int* __restrict__ rp_base,
                            int seg_in, int seg_out) {
    const int* cnt = cnt_base + (long long)blockIdx.x * seg_in;
    int* rowptr = rp_base + (long long)blockIdx.x * seg_out;
    __shared__ int warpsum[32];
    int t = threadIdx.x;                   // 1024, 4 elems each
    int v[4], s = 0;
#pragma unroll
    for (int j = 0; j < 4; j++) { v[j] = cnt[t * 4 + j]; s += v[j]; }
    int lane = t & 31, warp = t >> 5;
    int x = s;
#pragma unroll
    for (int o = 1; o < 32; o <<= 1) {
        int y = __shfl_up_sync(0xffffffffu, x, o);
        if (lane >= o) x += y;
    }
    if (lane == 31) warpsum[warp] = x;
    __syncthreads();
    if (warp == 0) {
        int w = warpsum[lane];
#pragma unroll
        for (int o = 1; o < 32; o <<= 1) {
            int y = __shfl_up_sync(0xffffffffu, w, o);
            if (lane >= o) w += y;
        }
        warpsum[lane] = w;
    }
    __syncthreads();
    int excl = x - s + (warp ? warpsum[warp - 1] : 0);
    int run = excl;
    if (t == 0) rowptr[0] = 0;
#pragma unroll
    for (int j = 0; j < 4; j++) { run += v[j]; rowptr[t * 4 + j + 1] = run; }
}

// ---------------- union CSR fill + per-e CSC fill ----------------
__global__ void fill_ext(const float* __restrict__ A, const int* __restrict__ rowptr,
                         const float* __restrict__ dis, int* __restrict__ col,
                         float* __restrict__ val, const int* __restrict__ cptr,
                         int* __restrict__ cfill, int* __restrict__ csrc,
                         float* __restrict__ cval) {
    int i = blockIdx.x;
    float di = dis[i];
    __shared__ int warpCnt[8];
    __shared__ int blockBase;
    if (threadIdx.x == 0) blockBase = rowptr[i];
    __syncthreads();
    for (int j0 = 0; j0 < N_NODES; j0 += 256) {
        int j = j0 + threadIdx.x;
        const float* ap = A + ((long long)i * N_NODES + j) * E_TYPES;
        float a[E_TYPES];
#pragma unroll
        for (int e = 0; e < E_TYPES; e++) a[e] = ap[e];
        bool nz = (j == i);
#pragma unroll
        for (int e = 0; e < E_TYPES; e++) nz |= (a[e] != 0.f);
        if (j != i) {
#pragma unroll
            for (int e = 0; e < E_TYPES; e++) {
                if (a[e] != 0.f) {
                    int slot = atomicAdd(&cfill[e * N_NODES + j], 1);
                    int pos = cptr[e * (N_NODES + 1) + j] + slot;
                    csrc[e * CAPE + pos] = i;
                    cval[e * CAPE + pos] = a[e];
                }
            }
        }
        unsigned mask = __ballot_sync(0xffffffffu, nz);
        int warp = threadIdx.x >> 5, lane = threadIdx.x & 31;
        if (lane == 0) warpCnt[warp] = __popc(mask);
        __syncthreads();
        int woff = 0;
        for (int w = 0; w < warp; w++) woff += warpCnt[w];
        int total = 0;
        for (int w = 0; w < 8; w++) total += warpCnt[w];
        if (nz) {
            int pos = blockBase + woff + __popc(mask & ((1u << lane) - 1));
            col[pos] = j;
            val[pos] = di * dis[j];
        }
        __syncthreads();
        if (threadIdx.x == 0) blockBase += total;
        __syncthreads();
    }
}

// ---------------- lgcn via per-e CSC gather ----------------
__global__ void lgcn_csc(const float* __restrict__ Xw, const int* __restrict__ csrc,
                         const float* __restrict__ cval, const int* __restrict__ cptr,
                         const float* __restrict__ degsum, float* __restrict__ lgcn) {
    int n = blockIdx.x, e = blockIdx.y, d = threadIdx.x;  // 128
    int s = cptr[e * (N_NODES + 1) + n], en = cptr[e * (N_NODES + 1) + n + 1];
    const int* cs = csrc + (long long)e * CAPE;
    const float* cv = cval + (long long)e * CAPE;
    float acc = Xw[(long long)n * W_OUT + d];
    for (int k = s; k < en; k++)
        acc += cv[k] * Xw[(long long)cs[k] * W_OUT + d];
    float dv = 1.f / (1.f + degsum[e * N_NODES + n]);
    lgcn[((long long)e * N_NODES + n) * W_OUT + d] = fmaxf(acc * dv, 0.f);
}

// ---------------- attention: two-stage ----------------
__global__ void att1(const float* __restrict__ lgcn, const float* __restrict__ attw,
                     float* __restrict__ attpart) {
    int g = blockIdx.x, e = blockIdx.y, d = threadIdx.x;  // ATT_G groups of 32
    float s = 0.f;
    int n0 = g * (N_NODES / ATT_G);
    for (int n = n0; n < n0 + N_NODES / ATT_G; n++)
        s += attw[n] * lgcn[((long long)e * N_NODES + n) * W_OUT + d];
    attpart[(e * ATT_G + g) * W_OUT + d] = s;
}

__global__ void att2(const float* __restrict__ attpart, const float* __restrict__ attb,
                     const float* __restrict__ attq, float* __restrict__ beta) {
    __shared__ float red[128];
    __shared__ float w[E_TYPES];
    int d = threadIdx.x;  // 128
    for (int e = 0; e < E_TYPES; e++) {
        float tot = 0.f;
#pragma unroll 8
        for (int g = 0; g < ATT_G; g++) tot += attpart[(e * ATT_G + g) * W_OUT + d];
        red[d] = tanhf(tot + attb[d]) * attq[d];
        __syncthreads();
        for (int o = 64; o; o >>= 1) {
            if (d < o) red[d] += red[d + o];
            __syncthreads();
        }
        if (d == 0) w[e] = red[0];
        __syncthreads();
    }
    if (d == 0) {
        float mx = w[0];
        for (int e = 1; e < E_TYPES; e++) mx = fmaxf(mx, w[e]);
        float ex[E_TYPES], s = 0.f;
        for (int e = 0; e < E_TYPES; e++) { ex[e] = expf(w[e] - mx); s += ex[e]; }
        for (int e = 0; e < E_TYPES; e++) beta[e] = (float)E_TYPES * ex[e] / s;
    }
}

// ---------------- X_ = [beta*lgcn (e-major) | X] ----------------
__global__ void xcat_kernel(const float* __restrict__ lgcn, const float* __restrict__ X,
                            const float* __restrict__ beta, float* __restrict__ Xcat) {
    long long idx = (long long)blockIdx.x * 256 + threadIdx.x;
    long long total = (long long)N_NODES * H0;
    if (idx >= total) return;
    int n = (int)(idx / H0), c = (int)(idx % H0);
    float v;
    if (c < E_TYPES * W_OUT) {
        int e = c >> 7, d = c & 127;
        v = beta[e] * lgcn[((long long)e * N_NODES + n) * W_OUT + d];
    } else {
        v = X[(long long)n * W_IN + (c - E_TYPES * W_OUT)];
    }
    Xcat[idx] = v;
}

// ---------------- fp32 -> fp16 convert ----------------
__global__ void f2h_kernel(const float* __restrict__ src, __half* __restrict__ dst, int n4) {
    int i = blockIdx.x * 256 + threadIdx.x;
    if (i >= n4) return;
    float4 v = ((const float4*)src)[i];
    __half2 h0 = __floats2half2_rn(v.x, v.y);
    __half2 h1 = __floats2half2_rn(v.z, v.w);
    ((float2*)dst)[i] = make_float2(h2_as_f(h0), h2_as_f(h1));
}

// ---------------- fused GCNII layer, 4 rows/block, 2 warps/row ----------------
// 256 threads = 8 warps; warps (2r, 2r+1) split row r0+r's nnz into even/odd 32-chunks.
// phase1: h = 0.9 * A_hat_row @ xh(fp16) + 0.1 * x0  -> hs[4][132]
// phase2: warp = (row, 64-col half); lane = 2 cols x full K
// out = relu((1-bl)*h + bl*(h @ Wl))
__global__ __launch_bounds__(256) void layer_fused4(
    const int* __restrict__ rowptr, const int* __restrict__ colp,
    const float* __restrict__ valp, const __half* __restrict__ xh,
    const float* __restrict__ x0, const float* __restrict__ Wl, float bl,
    float* __restrict__ xf_out, __half* __restrict__ xh_out) {
    __shared__ float hs[4][132];
    __shared__ float ps[4][128];
    __shared__ float Bs[32 * 128];
    int t = threadIdx.x;
    int warp = t >> 5, lane = t & 31;
    int rloc = warp >> 1, half = warp & 1;
    int row = blockIdx.x * 4 + rloc;
    int ks = rowptr[row], ke = rowptr[row + 1];
    float a0 = 0.f, a1 = 0.f, a2 = 0.f, a3 = 0.f;
    // gather: this warp handles 32-chunks at stride 64 starting at half*32
    for (int k0 = ks + half * 32; k0 < ke; k0 += 64) {
        int cnt = min(32, ke - k0);
        int cR = 0; float vR = 0.f;
        if (lane < cnt) { cR = colp[k0 + lane]; vR = valp[k0 + lane]; }
#pragma unroll 4
        for (int kk = 0; kk < cnt; kk++) {
            int c = __shfl_sync(0xffffffffu, cR, kk);
            float v = __shfl_sync(0xffffffffu, vR, kk);
            float2 raw = ((const float2*)(xh + (long long)c * W_OUT))[lane];
            __half2 p0 = *(__half2*)&raw.x;
            __half2 p1 = *(__half2*)&raw.y;
            float2 f0 = __half22float2(p0);
            float2 f1 = __half22float2(p1);
            a0 += v * f0.x; a1 += v * f0.y; a2 += v * f1.x; a3 += v * f1.y;
        }
    }
    if (half) {
        ps[rloc][lane * 4 + 0] = a0;
        ps[rloc][lane * 4 + 1] = a1;
        ps[rloc][lane * 4 + 2] = a2;
        ps[rloc][lane * 4 + 3] = a3;
    }
    __syncthreads();
    if (!half) {
        const float4 xv = ((const float4*)(x0 + (long long)row * W_OUT))[lane];
        hs[rloc][lane * 4 + 0] = 0.9f * (a0 + ps[rloc][lane * 4 + 0]) + 0.1f * xv.x;
        hs[rloc][lane * 4 + 1] = 0.9f * (a1 + ps[rloc][lane * 4 + 1]) + 0.1f * xv.y;
        hs[rloc][lane * 4 + 2] = 0.9f * (a2 + ps[rloc][lane * 4 + 2]) + 0.1f * xv.z;
        hs[rloc][lane * 4 + 3] = 0.9f * (a3 + ps[rloc][lane * 4 + 3]) + 0.1f * xv.w;
    }
    // dense: warp = (row rloc, col half); lane covers cols cb, cb+1
    int cb = half * 64 + lane * 2;
    float acc0 = 0.f, acc1 = 0.f;
    for (int k0 = 0; k0 < 128; k0 += 32) {
        __syncthreads();                   // first iter also publishes hs
#pragma unroll
        for (int i = 0; i < 4; i++) {
            int idx = t + 256 * i;         // 1024 float4 = 32x128
            int br = idx >> 5, bc = (idx & 31) << 2;
            *(float4*)(Bs + br * 128 + bc) = *(const float4*)(Wl + (long long)(k0 + br) * W_OUT + bc);
        }
        __syncthreads();
#pragma unroll
        for (int kk = 0; kk < 32; kk++) {
            float a = hs[rloc][k0 + kk];
            float2 b = *(const float2*)(Bs + kk * 128 + cb);
            acc0 += a * b.x; acc1 += a * b.y;
        }
    }
    float omb = 1.f - bl;
    float h0 = hs[rloc][cb], h1 = hs[rloc][cb + 1];
    float o0 = fmaxf(bl * acc0 + omb * h0, 0.f);
    float o1 = fmaxf(bl * acc1 + omb * h1, 0.f);
    if (xf_out)
        *(float2*)(xf_out + (long long)row * W_OUT + cb) = make_float2(o0, o1);
    if (xh_out) {
        __half2 q = __floats2half2_rn(o0, o1);
        *(unsigned*)(xh_out + (long long)row * W_OUT + cb) = *(unsigned*)&q;
    }
}

// ---------------- head ----------------
__global__ void out_kernel(const float* __restrict__ Z, const int* __restrict__ tx,
                           const float* __restrict__ W2, const float* __restrict__ b2,
                           float* __restrict__ y) {
    int r = blockIdx.x;
    int t = threadIdx.x;                   // 128
    __shared__ float z[W_OUT];
    z[t] = Z[(long long)tx[r] * W_OUT + t];
    __syncthreads();
    if (t < NUM_CLASS) {
        float s = b2[t];
        for (int k = 0; k < W_OUT; k++) s += z[k] * W2[k * NUM_CLASS + t];
        y[r * NUM_CLASS + t] = s;
    }
}

__global__ void loss_kernel(const float* __restrict__ y, const int* __restrict__ target,
                            float* __restrict__ out) {
    __shared__ float red[256];
    int tid = threadIdx.x;                 // 256
    float part = 0.f;
    for (int r = tid; r < M_TGT; r += 256) {
        const float* yr = y + r * NUM_CLASS;
        float mx = yr[0];
#pragma unroll
        for (int c = 1; c < NUM_CLASS; c++) mx = fmaxf(mx, yr[c]);
        float se = 0.f;
#pragma unroll
        for (int c = 0; c < NUM_CLASS; c++) se += expf(yr[c] - mx);
        float lse = mx + logf(se);
        part += lse - yr[target[r]];
    }
    red[tid] = part;
    __syncthreads();
    for (int o = 128; o; o >>= 1) {
        if (tid < o) red[tid] += red[tid + o];
        __syncthreads();
    }
    if (tid == 0) out[0] = red[0] / (float)M_TGT;
}

// ---------------- launch ----------------
extern "C" void kernel_launch(void* const* d_in, const int* in_sizes, int n_in,
                              void* d_out, int out_size) {
    const float* A        = (const float*)d_in[0];
    const float* X        = (const float*)d_in[1];
    const int*   target_x = (const int*)d_in[2];
    const int*   target   = (const int*)d_in[3];
    const float* weight   = (const float*)d_in[4];
    const float* attw     = (const float*)d_in[5];
    const float* attb     = (const float*)d_in[6];
    const float* attq     = (const float*)d_in[7];
    const float* Wg       = (const float*)d_in[8];
    const float* bg       = (const float*)d_in[9];
    const float* W0       = (const float*)d_in[10];
    const float* b0       = (const float*)d_in[11];
    const float* Wconvs   = (const float*)d_in[12];
    const float* Wd1      = (const float*)d_in[13];
    const float* bd1      = (const float*)d_in[14];
    const float* W1       = (const float*)d_in[15];
    const float* b1       = (const float*)d_in[16];
    const float* W2       = (const float*)d_in[17];
    const float* b2       = (const float*)d_in[18];

    float *Xg, *Xw, *lgcn, *attpart, *beta, *Xcat, *x0, *xlast, *Z1, *Z2, *ybuf;
    float *dis, *valp, *cvalp;
    __half *xh0, *xhA, *xhB;
    int *cnt, *rowptr, *colp, *zinit, *cptr, *csrcp;
    cudaGetSymbolAddress((void**)&Xg, g_Xg);
    cudaGetSymbolAddress((void**)&Xw, g_Xw);
    cudaGetSymbolAddress((void**)&lgcn, g_lgcn);
    cudaGetSymbolAddress((void**)&attpart, g_attpart);
    cudaGetSymbolAddress((void**)&beta, g_beta);
    cudaGetSymbolAddress((void**)&Xcat, g_Xcat);
    cudaGetSymbolAddress((void**)&x0, g_x0);
    cudaGetSymbolAddress((void**)&xlast, g_xlast);
    cudaGetSymbolAddress((void**)&xh0, g_xh0);
    cudaGetSymbolAddress((void**)&xhA, g_xhA);
    cudaGetSymbolAddress((void**)&xhB, g_xhB);
    cudaGetSymbolAddress((void**)&Z1, g_Z1);
    cudaGetSymbolAddress((void**)&Z2, g_Z2);
    cudaGetSymbolAddress((void**)&ybuf, g_y);
    cudaGetSymbolAddress((void**)&cnt, g_cnt);
    cudaGetSymbolAddress((void**)&rowptr, g_rowptr);
    cudaGetSymbolAddress((void**)&dis, g_dis);
    cudaGetSymbolAddress((void**)&colp, g_col);
    cudaGetSymbolAddress((void**)&valp, g_val);
    cudaGetSymbolAddress((void**)&zinit, g_zinit);
    cudaGetSymbolAddress((void**)&cptr, g_cptr);
    cudaGetSymbolAddress((void**)&csrcp, g_csrc);
    cudaGetSymbolAddress((void**)&cvalp, g_cval);

    int* ccnt = zinit;
    int* cfill = zinit + E_TYPES * N_NODES;
    float* degsum = (float*)(zinit + 2 * E_TYPES * N_NODES);

    cudaMemsetAsync(zinit, 0, 3 * E_TYPES * N_NODES * sizeof(int));

    // 1) Xg = leaky(X @ Wg + bg), Xw = leaky(Xg @ weight)
    gemm128<<<dim3(W_IN / 128, N_NODES / 128), 256>>>(X, Wg, Xg, N_NODES, W_IN, W_IN,
                                                      bg, nullptr, 1.f, 0.f, 2);
    gemm128<<<dim3(1, N_NODES / 128), 256>>>(Xg, weight, Xw, N_NODES, W_OUT, W_IN,
                                             nullptr, nullptr, 1.f, 0.f, 2);
    // 2) sparse structure build (union CSR + per-e CSC)
    rowcnt_ext<<<N_NODES, 256>>>(A, cnt, dis, ccnt, degsum);
    scan_kernel<<<1, 1024>>>(cnt, rowptr, 0, 0);
    scan_kernel<<<E_TYPES, 1024>>>(ccnt, cptr, N_NODES, N_NODES + 1);
    fill_ext<<<N_NODES, 256>>>(A, rowptr, dis, colp, valp, cptr, cfill, csrcp, cvalp);
    // 3) lgcn + attention + concat
    lgcn_csc<<<dim3(N_NODES, E_TYPES), 128>>>(Xw, csrcp, cvalp, cptr, degsum, lgcn);
    att1<<<dim3(ATT_G, E_TYPES), 128>>>(lgcn, attw, attpart);
    att2<<<1, 128>>>(attpart, attb, attq, beta);
    {
        long long total = (long long)N_NODES * H0;
        xcat_kernel<<<(unsigned)((total + 255) / 256), 256>>>(lgcn, X, beta, Xcat);
    }
    gemm128<<<dim3(1, N_NODES / 128), 256>>>(Xcat, W0, x0, N_NODES, W_OUT, H0,
                                             b0, nullptr, 1.f, 0.f, 1);
    f2h_kernel<<<(N_NODES * W_OUT / 4 + 255) / 256, 256>>>(x0, xh0, N_NODES * W_OUT / 4);
    // 4) 64 fused GCNII layers (fp16 activation carry; fp32 emitted on last layer only)
    const __half* xhin = xh0;
    __half* hbufs[2] = {xhA, xhB};
    for (int l = 0; l < NUM_LAYERS; l++) {
        float bl = logf(0.5f / (float)(l + 1) + 1.f);
        bool last = (l == NUM_LAYERS - 1);
        __half* xh = hbufs[l & 1];
        layer_fused4<<<N_NODES / 4, 256>>>(rowptr, colp, valp, xhin, x0,
                                           Wconvs + (long long)l * W_OUT * W_OUT, bl,
                                           last ? xlast : nullptr,
                                           last ? nullptr : xh);
        xhin = xh;
    }
    // 5) head
    gemm128<<<dim3(1, N_NODES / 128), 256>>>(xlast, Wd1, Z1, N_NODES, W_OUT, W_OUT,
                                             bd1, nullptr, 1.f, 0.f, 2);
    gemm128<<<dim3(1, N_NODES / 128), 256>>>(Z1, W1, Z2, N_NODES, W_OUT, W_OUT,
                                             b1, nullptr, 1.f, 0.f, 2);
    float* yout;
    bool with_loss;
    if (out_size >= M_TGT * NUM_CLASS + 1) { yout = (float*)d_out + 1; with_loss = true; }
    else if (out_size == M_TGT * NUM_CLASS) { yout = (float*)d_out; with_loss = false; }
    else { yout = ybuf; with_loss = true; }
    out_kernel<<<M_TGT, 128>>>(Z2, target_x, W2, b2, yout);
    if (with_loss) loss_kernel<<<1, 256>>>(yout, target, (float*)d_out);
}